// round 7
// baseline (speedup 1.0000x reference)
#include <cuda_runtime.h>
#include <cstdint>

#define BB       8
#define NN       8192
#define NPOINT   1024
#define NSAMPLE  32
#define CFEAT    64
#define CIN0     67      // 3 + 64

// ------------------------------------------------------------------
// scratch (no allocations allowed)
// ------------------------------------------------------------------
__device__ int g_gidx[BB * NPOINT * NSAMPLE];
// FPS cross-CTA sync slots: [batch][parity][cta], padded to 128B each
// (16 u64).  Zero-initialized at module load; stale contents from
// prior graph replays are benign (deterministic recomputation yields
// identical values, so an early tag-match reads the correct data).
__device__ unsigned long long g_fps_slot[BB * 2 * 32 * 16];

// ------------------------------------------------------------------
// packed f32x2 helpers (Blackwell sm_103a)
// ------------------------------------------------------------------
__device__ __forceinline__ unsigned long long pk2(float lo, float hi) {
    unsigned long long r;
    asm("mov.b64 %0, {%1, %2};" : "=l"(r) : "f"(lo), "f"(hi));
    return r;
}
__device__ __forceinline__ void upk2(unsigned long long v, float& lo, float& hi) {
    asm("mov.b64 {%0, %1}, %2;" : "=f"(lo), "=f"(hi) : "l"(v));
}
__device__ __forceinline__ unsigned long long add2_(unsigned long long a, unsigned long long b) {
    unsigned long long r;
    asm("add.rn.f32x2 %0, %1, %2;" : "=l"(r) : "l"(a), "l"(b));
    return r;
}
__device__ __forceinline__ unsigned long long mul2_(unsigned long long a, unsigned long long b) {
    unsigned long long r;
    asm("mul.rn.f32x2 %0, %1, %2;" : "=l"(r) : "l"(a), "l"(b));
    return r;
}
__device__ __forceinline__ unsigned long long fma2_(unsigned long long a, unsigned long long b,
                                                    unsigned long long c) {
    unsigned long long r;
    asm("fma.rn.f32x2 %0, %1, %2, %3;" : "=l"(r) : "l"(a), "l"(b), "l"(c));
    return r;
}
__device__ __forceinline__ unsigned long long ld_acq(const unsigned long long* p) {
    unsigned long long v;
    asm volatile("ld.acquire.gpu.b64 %0, [%1];" : "=l"(v) : "l"(p) : "memory");
    return v;
}
__device__ __forceinline__ void st_rel(unsigned long long* p, unsigned long long v) {
    asm volatile("st.release.gpu.b64 [%0], %1;" :: "l"(p), "l"(v) : "memory");
}

// ==================================================================
// Kernel 1: FPS, 32 CTAs per batch (1 warp each, 256 pts, 8/thread),
// gmem release/acquire sync per iteration.
//  - each CTA holds the FULL batch xyz in smem (96KB, 2 CTAs/SM,
//    all 256 CTAs resident -> no scheduling deadlock)
//  - per iter: local mind update -> warp REDUX partial
//    -> lane0 st.release (val<<32 | idx<<10 | tag) into own slot
//    -> lane i acquire-polls CTA i's slot until tag matches
//    -> REDUX max val, REDUX min idx among ties  (== reference argmax)
//    -> q coords from local smem copy
//  - parity-2 slot buffering: a CTA overwrites parity p only at it+2,
//    by which time every peer has passed poll(it) (proof: passing
//    poll(it+1) requires all peers wrote tag it+1, which happens only
//    after they exited poll(it)).
// Arithmetic bit-matches the reference (rn ops, no fma contraction,
// first-max-index tiebreak).
// ==================================================================
__global__ void __launch_bounds__(32, 1)
fps_kernel(const float* __restrict__ xyz, float* __restrict__ newxyz)
{
    extern __shared__ float sm[];
    float* sx = sm;
    float* sy = sm + NN;
    float* sz = sm + 2 * NN;

    const int b = blockIdx.y;
    const int c = blockIdx.x;          // CTA index within batch (0..31)
    const int lane = threadIdx.x;
    const float* bx = xyz + (size_t)b * NN * 3;
    float* out = newxyz + (size_t)b * NPOINT * 3;

    // full batch xyz -> smem (one-time)
    for (int i = lane; i < NN; i += 32) {
        sx[i] = bx[3 * i + 0];
        sy[i] = bx[3 * i + 1];
        sz[i] = bx[3 * i + 2];
    }
    __syncthreads();

    const int base = c * 256 + lane * 8;
    unsigned long long px2[4], py2[4], pz2[4];
    float mind[8];
#pragma unroll
    for (int k = 0; k < 4; k++) {
        px2[k] = pk2(sx[base + 2 * k], sx[base + 2 * k + 1]);
        py2[k] = pk2(sy[base + 2 * k], sy[base + 2 * k + 1]);
        pz2[k] = pk2(sz[base + 2 * k], sz[base + 2 * k + 1]);
        mind[2 * k] = 1e10f;
        mind[2 * k + 1] = 1e10f;
    }

    float qx = sx[0], qy = sy[0], qz = sz[0];
    if (c == 0 && lane == 0) { out[0] = qx; out[1] = qy; out[2] = qz; }

    for (int it = 1; it < NPOINT; it++) {
        const unsigned long long nqx = pk2(-qx, -qx);
        const unsigned long long nqy = pk2(-qy, -qy);
        const unsigned long long nqz = pk2(-qz, -qz);
#pragma unroll
        for (int k = 0; k < 4; k++) {
            unsigned long long dx = add2_(px2[k], nqx);
            unsigned long long dy = add2_(py2[k], nqy);
            unsigned long long dz = add2_(pz2[k], nqz);
            unsigned long long d2 = add2_(add2_(mul2_(dx, dx), mul2_(dy, dy)),
                                          mul2_(dz, dz));
            float d0, d1;
            upk2(d2, d0, d1);
            mind[2 * k]     = fminf(mind[2 * k], d0);
            mind[2 * k + 1] = fminf(mind[2 * k + 1], d1);
        }
        float vloc = fmaxf(fmaxf(fmaxf(mind[0], mind[1]), fmaxf(mind[2], mind[3])),
                           fmaxf(fmaxf(mind[4], mind[5]), fmaxf(mind[6], mind[7])));

        // warp partial: max value (uint order == float order for >=0),
        // then first (lowest) index attaining it
        unsigned wmax = __reduce_max_sync(0xffffffffu, __float_as_uint(vloc));
        float wmaxf = __uint_as_float(wmax);
        unsigned idxl = 0xffffffffu;
#pragma unroll
        for (int j = 7; j >= 0; j--)
            if (mind[j] == wmaxf) idxl = base + j;
        unsigned widx = __reduce_min_sync(0xffffffffu, idxl);

        // publish + poll
        const unsigned tag = (unsigned)it;       // < 1024, fits 10 bits
        unsigned long long* sb = g_fps_slot + (size_t)((b * 2 + (it & 1)) * 32) * 16;
        if (lane == 0)
            st_rel(sb + (size_t)c * 16,
                   ((unsigned long long)wmax << 32) |
                   ((unsigned long long)widx << 10) | tag);

        const unsigned long long* mp = sb + (size_t)lane * 16;
        unsigned long long w;
        do { w = ld_acq(mp); } while ((unsigned)(w & 1023u) != tag);

        unsigned val = (unsigned)(w >> 32);
        unsigned idx = (unsigned)((w >> 10) & 0x1FFFu);
        unsigned vmax = __reduce_max_sync(0xffffffffu, val);
        unsigned bi   = __reduce_min_sync(0xffffffffu,
                                          (val == vmax) ? idx : 0xffffffffu);

        qx = sx[bi]; qy = sy[bi]; qz = sz[bi];
        if (c == 0 && lane == 0) {
            out[it * 3 + 0] = qx;
            out[it * 3 + 1] = qy;
            out[it * 3 + 2] = qz;
        }
    }
}

// ==================================================================
// Kernel 2: ball query (unchanged)
// ==================================================================
__global__ void __launch_bounds__(256)
ballquery_kernel(const float* __restrict__ xyz, const float* __restrict__ newxyz)
{
    const int gw   = (blockIdx.x * blockDim.x + threadIdx.x) >> 5;
    const int lane = threadIdx.x & 31;
    if (gw >= BB * NPOINT) return;
    const int b = gw >> 10;
    const float* bx = xyz + (size_t)b * NN * 3;
    const float cx = newxyz[gw * 3 + 0];
    const float cy = newxyz[gw * 3 + 1];
    const float cz = newxyz[gw * 3 + 2];
    int* out = g_gidx + gw * NSAMPLE;
    const float R2 = (float)0.04;

    int cnt = 0, firstIdx = 0;
    for (int base = 0; base < NN; base += 32) {
        const int i = base + lane;
        float dx = __fsub_rn(bx[i * 3 + 0], cx);
        float dy = __fsub_rn(bx[i * 3 + 1], cy);
        float dz = __fsub_rn(bx[i * 3 + 2], cz);
        float d  = __fadd_rn(__fadd_rn(__fmul_rn(dx, dx), __fmul_rn(dy, dy)),
                             __fmul_rn(dz, dz));
        bool in = d < R2;
        unsigned mask = __ballot_sync(0xffffffffu, in);
        if (mask) {
            if (cnt == 0) firstIdx = base + (__ffs(mask) - 1);
            if (in) {
                int slot = cnt + __popc(mask & ((1u << lane) - 1u));
                if (slot < NSAMPLE) out[slot] = i;
            }
            cnt += __popc(mask);
            if (cnt >= NSAMPLE) break;
        }
    }
    if (lane >= cnt) out[lane] = (cnt > 0) ? firstIdx : 0;
}

// ==================================================================
// Kernel 3: MLP (unchanged from R6 — measured best).
// Warp = one group, thread = 4 samples x 16 channels.
// ==================================================================
#define MLP_T   512
#define GPB     16               // groups per block (= warps)
#define RPITCH  67               // 67 % 32 = 3 -> 8 samples hit 8 banks
#define W0SL    (CIN0 * 16 + 4)  // 1076 floats per slice (skewed)
#define W1SL    (64 * 16 + 4)    // 1028
#define W2SL    (64 * 16 + 4)    // 1028

__global__ void __launch_bounds__(MLP_T, 1)
mlp_kernel(const float* __restrict__ xyz, const float* __restrict__ feat,
           const float* __restrict__ w0, const float* __restrict__ s0g, const float* __restrict__ b0g,
           const float* __restrict__ w1, const float* __restrict__ s1g, const float* __restrict__ b1g,
           const float* __restrict__ w2, const float* __restrict__ s2g, const float* __restrict__ b2g,
           const float* __restrict__ newxyz, float* __restrict__ outfeat)
{
    extern __shared__ float sm[];
    float* w0v = sm;                    // 4 slices x W0SL
    float* w1v = w0v + 4 * W0SL;        // 4 slices x W1SL
    float* w2v = w1v + 4 * W1SL;        // 8 slices x W2SL
    float* sc0 = w2v + 8 * W2SL;
    float* bi0 = sc0 + 64;
    float* sc1 = bi0 + 64;
    float* bi1 = sc1 + 64;
    float* sc2 = bi1 + 64;              // 128
    float* bi2 = sc2 + 128;             // 128
    float* xr  = bi2 + 128;             // GPB * 32 * RPITCH

    const int t = threadIdx.x;
    const int lane = t & 31;
    const int g = t >> 5;               // group (warp) within block
    const int q = lane & 7;             // sample quad id (samples 4q..4q+3)
    const int s = lane >> 3;            // channel-slice id (0..3)

    // ---- weight load: slice-major [slice][c][16] with +4 skew ----
    for (int i = t; i < 4 * CIN0 * 16; i += MLP_T) {
        int sl = i / (CIN0 * 16), r = i - sl * (CIN0 * 16);
        int c = r >> 4, k = r & 15;
        w0v[sl * W0SL + r] = w0[(sl * 16 + k) * CIN0 + c];
    }
    for (int i = t; i < 4 * 64 * 16; i += MLP_T) {
        int sl = i >> 10, r = i & 1023;
        int c = r >> 4, k = r & 15;
        w1v[sl * W1SL + r] = w1[(sl * 16 + k) * 64 + c];
    }
    for (int i = t; i < 8 * 64 * 16; i += MLP_T) {
        int sl = i >> 10, r = i & 1023;
        int c = r >> 4, k = r & 15;
        w2v[sl * W2SL + r] = w2[(sl * 16 + k) * 64 + c];
    }
    if (t < 64)  { sc0[t] = s0g[t]; bi0[t] = b0g[t]; sc1[t] = s1g[t]; bi1[t] = b1g[t]; }
    if (t < 128) { sc2[t] = s2g[t]; bi2[t] = b2g[t]; }
    __syncthreads();

    const int gi = blockIdx.x * GPB + g;
    const int b  = gi >> 10;
    const int sidx = gi & 1023;
    float* xg = xr + g * 32 * RPITCH;

    // ---- gather: this thread fills rows of its 4 samples ----
    {
        const float cx = newxyz[gi * 3 + 0];
        const float cy = newxyz[gi * 3 + 1];
        const float cz = newxyz[gi * 3 + 2];
#pragma unroll
        for (int j = 0; j < 4; j++) {
            const int n = 4 * q + j;
            const int pi = g_gidx[gi * NSAMPLE + n];
            float* row = xg + n * RPITCH;
            const float* prow = xyz + ((size_t)b * NN + pi) * 3;
            row[0] = __fsub_rn(prow[0], cx);
            row[1] = __fsub_rn(prow[1], cy);
            row[2] = __fsub_rn(prow[2], cz);
            const float4* frow = (const float4*)(feat + ((size_t)b * NN + pi) * CFEAT);
#pragma unroll
            for (int k = 0; k < 16; k++) {
                float4 f = frow[k];
                row[3 + 4 * k + 0] = f.x;
                row[3 + 4 * k + 1] = f.y;
                row[3 + 4 * k + 2] = f.z;
                row[3 + 4 * k + 3] = f.w;
            }
        }
    }
    __syncwarp();

    unsigned long long acc[32];     // acc[j*8+u]: sample j, channels sbase+2u(+1)
    const int chb = s * 16;

    // ---- layer 0: 67 -> 64 ----
    {
        const float* wb = w0v + s * W0SL;
#pragma unroll
        for (int i = 0; i < 32; i++) acc[i] = 0ull;
#pragma unroll 1
        for (int c = 0; c < CIN0; c++) {
            const ulonglong2* wr = (const ulonglong2*)(wb + c * 16);
            ulonglong2 wA = wr[0], wB = wr[1];
            unsigned long long x0 = pk2(xg[(4 * q + 0) * RPITCH + c], xg[(4 * q + 0) * RPITCH + c]);
            unsigned long long x1 = pk2(xg[(4 * q + 1) * RPITCH + c], xg[(4 * q + 1) * RPITCH + c]);
            unsigned long long x2 = pk2(xg[(4 * q + 2) * RPITCH + c], xg[(4 * q + 2) * RPITCH + c]);
            unsigned long long x3 = pk2(xg[(4 * q + 3) * RPITCH + c], xg[(4 * q + 3) * RPITCH + c]);
            acc[0]  = fma2_(x0, wA.x, acc[0]);  acc[1]  = fma2_(x0, wA.y, acc[1]);
            acc[2]  = fma2_(x0, wB.x, acc[2]);  acc[3]  = fma2_(x0, wB.y, acc[3]);
            acc[8]  = fma2_(x1, wA.x, acc[8]);  acc[9]  = fma2_(x1, wA.y, acc[9]);
            acc[10] = fma2_(x1, wB.x, acc[10]); acc[11] = fma2_(x1, wB.y, acc[11]);
            acc[16] = fma2_(x2, wA.x, acc[16]); acc[17] = fma2_(x2, wA.y, acc[17]);
            acc[18] = fma2_(x2, wB.x, acc[18]); acc[19] = fma2_(x2, wB.y, acc[19]);
            acc[24] = fma2_(x3, wA.x, acc[24]); acc[25] = fma2_(x3, wA.y, acc[25]);
            acc[26] = fma2_(x3, wB.x, acc[26]); acc[27] = fma2_(x3, wB.y, acc[27]);
            const ulonglong2* wr2 = (const ulonglong2*)(wb + c * 16 + 8);
            ulonglong2 wC = wr2[0], wD = wr2[1];
            acc[4]  = fma2_(x0, wC.x, acc[4]);  acc[5]  = fma2_(x0, wC.y, acc[5]);
            acc[6]  = fma2_(x0, wD.x, acc[6]);  acc[7]  = fma2_(x0, wD.y, acc[7]);
            acc[12] = fma2_(x1, wC.x, acc[12]); acc[13] = fma2_(x1, wC.y, acc[13]);
            acc[14] = fma2_(x1, wD.x, acc[14]); acc[15] = fma2_(x1, wD.y, acc[15]);
            acc[20] = fma2_(x2, wC.x, acc[20]); acc[21] = fma2_(x2, wC.y, acc[21]);
            acc[22] = fma2_(x2, wD.x, acc[22]); acc[23] = fma2_(x2, wD.y, acc[23]);
            acc[28] = fma2_(x3, wC.x, acc[28]); acc[29] = fma2_(x3, wC.y, acc[29]);
            acc[30] = fma2_(x3, wD.x, acc[30]); acc[31] = fma2_(x3, wD.y, acc[31]);
        }
        __syncwarp();
#pragma unroll
        for (int j = 0; j < 4; j++) {
            float* row = xg + (4 * q + j) * RPITCH;
#pragma unroll
            for (int u = 0; u < 8; u++) {
                float a0, a1;
                upk2(acc[j * 8 + u], a0, a1);
                int oc = chb + 2 * u;
                float v0 = __fadd_rn(__fmul_rn(a0, sc0[oc]),     bi0[oc]);
                float v1 = __fadd_rn(__fmul_rn(a1, sc0[oc + 1]), bi0[oc + 1]);
                row[oc]     = fmaxf(v0, 0.0f);
                row[oc + 1] = fmaxf(v1, 0.0f);
            }
        }
        __syncwarp();
    }

    // ---- layer 1: 64 -> 64 ----
    {
        const float* wb = w1v + s * W1SL;
#pragma unroll
        for (int i = 0; i < 32; i++) acc[i] = 0ull;
#pragma unroll 1
        for (int c = 0; c < 64; c++) {
            const ulonglong2* wr = (const ulonglong2*)(wb + c * 16);
            ulonglong2 wA = wr[0], wB = wr[1];
            unsigned long long x0 = pk2(xg[(4 * q + 0) * RPITCH + c], xg[(4 * q + 0) * RPITCH + c]);
            unsigned long long x1 = pk2(xg[(4 * q + 1) * RPITCH + c], xg[(4 * q + 1) * RPITCH + c]);
            unsigned long long x2 = pk2(xg[(4 * q + 2) * RPITCH + c], xg[(4 * q + 2) * RPITCH + c]);
            unsigned long long x3 = pk2(xg[(4 * q + 3) * RPITCH + c], xg[(4 * q + 3) * RPITCH + c]);
            acc[0]  = fma2_(x0, wA.x, acc[0]);  acc[1]  = fma2_(x0, wA.y, acc[1]);
            acc[2]  = fma2_(x0, wB.x, acc[2]);  acc[3]  = fma2_(x0, wB.y, acc[3]);
            acc[8]  = fma2_(x1, wA.x, acc[8]);  acc[9]  = fma2_(x1, wA.y, acc[9]);
            acc[10] = fma2_(x1, wB.x, acc[10]); acc[11] = fma2_(x1, wB.y, acc[11]);
            acc[16] = fma2_(x2, wA.x, acc[16]); acc[17] = fma2_(x2, wA.y, acc[17]);
            acc[18] = fma2_(x2, wB.x, acc[18]); acc[19] = fma2_(x2, wB.y, acc[19]);
            acc[24] = fma2_(x3, wA.x, acc[24]); acc[25] = fma2_(x3, wA.y, acc[25]);
            acc[26] = fma2_(x3, wB.x, acc[26]); acc[27] = fma2_(x3, wB.y, acc[27]);
            const ulonglong2* wr2 = (const ulonglong2*)(wb + c * 16 + 8);
            ulonglong2 wC = wr2[0], wD = wr2[1];
            acc[4]  = fma2_(x0, wC.x, acc[4]);  acc[5]  = fma2_(x0, wC.y, acc[5]);
            acc[6]  = fma2_(x0, wD.x, acc[6]);  acc[7]  = fma2_(x0, wD.y, acc[7]);
            acc[12] = fma2_(x1, wC.x, acc[12]); acc[13] = fma2_(x1, wC.y, acc[13]);
            acc[14] = fma2_(x1, wD.x, acc[14]); acc[15] = fma2_(x1, wD.y, acc[15]);
            acc[20] = fma2_(x2, wC.x, acc[20]); acc[21] = fma2_(x2, wC.y, acc[21]);
            acc[22] = fma2_(x2, wD.x, acc[22]); acc[23] = fma2_(x2, wD.y, acc[23]);
            acc[28] = fma2_(x3, wC.x, acc[28]); acc[29] = fma2_(x3, wC.y, acc[29]);
            acc[30] = fma2_(x3, wD.x, acc[30]); acc[31] = fma2_(x3, wD.y, acc[31]);
        }
        __syncwarp();
#pragma unroll
        for (int j = 0; j < 4; j++) {
            float* row = xg + (4 * q + j) * RPITCH;
#pragma unroll
            for (int u = 0; u < 8; u++) {
                float a0, a1;
                upk2(acc[j * 8 + u], a0, a1);
                int oc = chb + 2 * u;
                float v0 = __fadd_rn(__fmul_rn(a0, sc1[oc]),     bi1[oc]);
                float v1 = __fadd_rn(__fmul_rn(a1, sc1[oc + 1]), bi1[oc + 1]);
                row[oc]     = fmaxf(v0, 0.0f);
                row[oc + 1] = fmaxf(v1, 0.0f);
            }
        }
        __syncwarp();
    }

    // ---- layer 2: 64 -> 128 in 2 rounds; reduce-scatter maxpool ----
    const size_t outbase = (size_t)b * 128 * NPOINT + sidx;
    const int q2 = (q >> 2) & 1, q1 = (q >> 1) & 1, q0 = q & 1;
#pragma unroll 1
    for (int r = 0; r < 2; r++) {
        const int p = s + 4 * r;              // slice 0..7
        const float* wb = w2v + p * W2SL;
#pragma unroll
        for (int i = 0; i < 32; i++) acc[i] = 0ull;
#pragma unroll 1
        for (int c = 0; c < 64; c++) {
            const ulonglong2* wr = (const ulonglong2*)(wb + c * 16);
            ulonglong2 wA = wr[0], wB = wr[1];
            unsigned long long x0 = pk2(xg[(4 * q + 0) * RPITCH + c], xg[(4 * q + 0) * RPITCH + c]);
            unsigned long long x1 = pk2(xg[(4 * q + 1) * RPITCH + c], xg[(4 * q + 1) * RPITCH + c]);
            unsigned long long x2 = pk2(xg[(4 * q + 2) * RPITCH + c], xg[(4 * q + 2) * RPITCH + c]);
            unsigned long long x3 = pk2(xg[(4 * q + 3) * RPITCH + c], xg[(4 * q + 3) * RPITCH + c]);
            acc[0]  = fma2_(x0, wA.x, acc[0]);  acc[1]  = fma2_(x0, wA.y, acc[1]);
            acc[2]  = fma2_(x0, wB.x, acc[2]);  acc[3]  = fma2_(x0, wB.y, acc[3]);
            acc[8]  = fma2_(x1, wA.x, acc[8]);  acc[9]  = fma2_(x1, wA.y, acc[9]);
            acc[10] = fma2_(x1, wB.x, acc[10]); acc[11] = fma2_(x1, wB.y, acc[11]);
            acc[16] = fma2_(x2, wA.x, acc[16]); acc[17] = fma2_(x2, wA.y, acc[17]);
            acc[18] = fma2_(x2, wB.x, acc[18]); acc[19] = fma2_(x2, wB.y, acc[19]);
            acc[24] = fma2_(x3, wA.x, acc[24]); acc[25] = fma2_(x3, wA.y, acc[25]);
            acc[26] = fma2_(x3, wB.x, acc[26]); acc[27] = fma2_(x3, wB.y, acc[27]);
            const ulonglong2* wr2 = (const ulonglong2*)(wb + c * 16 + 8);
            ulonglong2 wC = wr2[0], wD = wr2[1];
            acc[4]  = fma2_(x0, wC.x, acc[4]);  acc[5]  = fma2_(x0, wC.y, acc[5]);
            acc[6]  = fma2_(x0, wD.x, acc[6]);  acc[7]  = fma2_(x0, wD.y, acc[7]);
            acc[12] = fma2_(x1, wC.x, acc[12]); acc[13] = fma2_(x1, wC.y, acc[13]);
            acc[14] = fma2_(x1, wD.x, acc[14]); acc[15] = fma2_(x1, wD.y, acc[15]);
            acc[20] = fma2_(x2, wC.x, acc[20]); acc[21] = fma2_(x2, wC.y, acc[21]);
            acc[22] = fma2_(x2, wD.x, acc[22]); acc[23] = fma2_(x2, wD.y, acc[23]);
            acc[28] = fma2_(x3, wC.x, acc[28]); acc[29] = fma2_(x3, wC.y, acc[29]);
            acc[30] = fma2_(x3, wD.x, acc[30]); acc[31] = fma2_(x3, wD.y, acc[31]);
        }
        // per-thread: scale/bias/relu + max over own 4 samples
        float vm[16];
#pragma unroll
        for (int u = 0; u < 8; u++) {
            int oc = p * 16 + 2 * u;
            float scA = sc2[oc], biA = bi2[oc], scB = sc2[oc + 1], biB = bi2[oc + 1];
            float m0 = 0.0f, m1 = 0.0f;   // relu floor
#pragma unroll
            for (int j = 0; j < 4; j++) {
                float a0, a1;
                upk2(acc[j * 8 + u], a0, a1);
                float v0 = __fadd_rn(__fmul_rn(a0, scA), biA);
                float v1 = __fadd_rn(__fmul_rn(a1, scB), biB);
                m0 = fmaxf(m0, fmaxf(v0, 0.0f));
                m1 = fmaxf(m1, fmaxf(v1, 0.0f));
            }
            vm[2 * u] = m0; vm[2 * u + 1] = m1;
        }
        // reduce-scatter across 8 quads: lane q ends with ch {2q, 2q+1}
        float B8[8];
#pragma unroll
        for (int i = 0; i < 8; i++) {
            float snd = q2 ? vm[i] : vm[8 + i];
            float got = __shfl_xor_sync(0xffffffffu, snd, 4);
            float kp  = q2 ? vm[8 + i] : vm[i];
            B8[i] = fmaxf(kp, got);
        }
        float C4[4];
#pragma unroll
        for (int i = 0; i < 4; i++) {
            float snd = q1 ? B8[i] : B8[4 + i];
            float got = __shfl_xor_sync(0xffffffffu, snd, 2);
            float kp  = q1 ? B8[4 + i] : B8[i];
            C4[i] = fmaxf(kp, got);
        }
        float D0, D1;
        {
            float snd = q0 ? C4[0] : C4[2];
            float got = __shfl_xor_sync(0xffffffffu, snd, 1);
            float kp  = q0 ? C4[2] : C4[0];
            D0 = fmaxf(kp, got);
            snd = q0 ? C4[1] : C4[3];
            got = __shfl_xor_sync(0xffffffffu, snd, 1);
            kp  = q0 ? C4[3] : C4[1];
            D1 = fmaxf(kp, got);
        }
        const int ch = p * 16 + 2 * q;
        outfeat[outbase + (size_t)ch * NPOINT]       = D0;
        outfeat[outbase + (size_t)(ch + 1) * NPOINT] = D1;
    }
}

// ==================================================================
// launch
// ==================================================================
extern "C" void kernel_launch(void* const* d_in, const int* in_sizes, int n_in,
                              void* d_out, int out_size)
{
    (void)in_sizes; (void)n_in; (void)out_size;
    const float* xyz  = (const float*)d_in[0];
    const float* feat = (const float*)d_in[1];
    const float* w0 = (const float*)d_in[2];
    const float* s0 = (const float*)d_in[3];
    const float* b0 = (const float*)d_in[4];
    const float* w1 = (const float*)d_in[5];
    const float* s1 = (const float*)d_in[6];
    const float* b1 = (const float*)d_in[7];
    const float* w2 = (const float*)d_in[8];
    const float* s2 = (const float*)d_in[9];
    const float* b2 = (const float*)d_in[10];

    float* out     = (float*)d_out;
    float* newxyz  = out;                            // (B, NPOINT, 3)
    float* outfeat = out + (size_t)BB * NPOINT * 3;  // (B, 128, NPOINT)

    const int FPS_SMEM = 3 * NN * 4;                  // 98304 B
    const int MLP_SMEM = (4 * W0SL + 4 * W1SL + 8 * W2SL + 512 +
                          GPB * 32 * RPITCH) * 4;
    cudaFuncSetAttribute(fps_kernel, cudaFuncAttributeMaxDynamicSharedMemorySize, FPS_SMEM);
    cudaFuncSetAttribute(mlp_kernel, cudaFuncAttributeMaxDynamicSharedMemorySize, MLP_SMEM);

    dim3 fgrid(32, BB);
    fps_kernel<<<fgrid, 32, FPS_SMEM>>>(xyz, newxyz);
    ballquery_kernel<<<(BB * NPOINT * 32) / 256, 256>>>(xyz, newxyz);
    mlp_kernel<<<BB * NPOINT / GPB, MLP_T, MLP_SMEM>>>(
        xyz, feat, w0, s0, b0, w1, s1, b1, w2, s2, b2, newxyz, outfeat);
}

// round 8
// speedup vs baseline: 2.4280x; 2.4280x over previous
#include <cuda_runtime.h>
#include <cstdint>

#define BB       8
#define NN       8192
#define NPOINT   1024
#define NSAMPLE  32
#define CFEAT    64
#define CIN0     67      // 3 + 64

// ------------------------------------------------------------------
// scratch (no allocations allowed) : ball-query group indices
// ------------------------------------------------------------------
__device__ int g_gidx[BB * NPOINT * NSAMPLE];

// ------------------------------------------------------------------
// packed f32x2 helpers (Blackwell sm_103a)
// ------------------------------------------------------------------
__device__ __forceinline__ unsigned long long pk2(float lo, float hi) {
    unsigned long long r;
    asm("mov.b64 %0, {%1, %2};" : "=l"(r) : "f"(lo), "f"(hi));
    return r;
}
__device__ __forceinline__ void upk2(unsigned long long v, float& lo, float& hi) {
    asm("mov.b64 {%0, %1}, %2;" : "=f"(lo), "=f"(hi) : "l"(v));
}
__device__ __forceinline__ unsigned long long add2_(unsigned long long a, unsigned long long b) {
    unsigned long long r;
    asm("add.rn.f32x2 %0, %1, %2;" : "=l"(r) : "l"(a), "l"(b));
    return r;
}
__device__ __forceinline__ unsigned long long mul2_(unsigned long long a, unsigned long long b) {
    unsigned long long r;
    asm("mul.rn.f32x2 %0, %1, %2;" : "=l"(r) : "l"(a), "l"(b));
    return r;
}
__device__ __forceinline__ unsigned long long fma2_(unsigned long long a, unsigned long long b,
                                                    unsigned long long c) {
    unsigned long long r;
    asm("fma.rn.f32x2 %0, %1, %2, %3;" : "=l"(r) : "l"(a), "l"(b), "l"(c));
    return r;
}

// ==================================================================
// Kernel 1: FPS (R6 proven config — 512 thr/block, 1 block/batch,
// single barrier per iter, double-buffered partials). Bit-exact.
// ==================================================================
#define FPS_T 512
#define FPS_P (NN / FPS_T)   // 16

__global__ void __launch_bounds__(FPS_T, 1)
fps_kernel(const float* __restrict__ xyz, float* __restrict__ newxyz)
{
    extern __shared__ float sm[];
    float* sx = sm;
    float* sy = sm + NN;
    float* sz = sm + 2 * NN;
    unsigned* wv = (unsigned*)(sm + 3 * NN);   // [2][16]
    unsigned* wi = wv + 32;                    // [2][16]

    const int b = blockIdx.x;
    const float* bx = xyz + (size_t)b * NN * 3;
    float* out = newxyz + (size_t)b * NPOINT * 3;
    const int t = threadIdx.x;
    const int lane = t & 31;
    const int warp = t >> 5;

    unsigned long long px2[FPS_P / 2], py2[FPS_P / 2], pz2[FPS_P / 2];
    float mind[FPS_P];
#pragma unroll
    for (int k = 0; k < FPS_P / 2; k++) {
        int i0 = t * FPS_P + 2 * k;
        int i1 = i0 + 1;
        float x0 = bx[i0 * 3 + 0], y0 = bx[i0 * 3 + 1], z0 = bx[i0 * 3 + 2];
        float x1 = bx[i1 * 3 + 0], y1 = bx[i1 * 3 + 1], z1 = bx[i1 * 3 + 2];
        px2[k] = pk2(x0, x1); py2[k] = pk2(y0, y1); pz2[k] = pk2(z0, z1);
        sx[i0] = x0; sy[i0] = y0; sz[i0] = z0;
        sx[i1] = x1; sy[i1] = y1; sz[i1] = z1;
        mind[2 * k] = 1e10f; mind[2 * k + 1] = 1e10f;
    }
    __syncthreads();

    float qx = sx[0], qy = sy[0], qz = sz[0];
    if (t == 0) { out[0] = qx; out[1] = qy; out[2] = qz; }

    for (int it = 1; it < NPOINT; it++) {
        const unsigned long long nqx = pk2(-qx, -qx);
        const unsigned long long nqy = pk2(-qy, -qy);
        const unsigned long long nqz = pk2(-qz, -qz);
        float vloc = -1.0f;
#pragma unroll
        for (int k = 0; k < FPS_P / 2; k++) {
            unsigned long long dx = add2_(px2[k], nqx);
            unsigned long long dy = add2_(py2[k], nqy);
            unsigned long long dz = add2_(pz2[k], nqz);
            unsigned long long d2 = add2_(add2_(mul2_(dx, dx), mul2_(dy, dy)),
                                          mul2_(dz, dz));
            float d0, d1;
            upk2(d2, d0, d1);
            float m0 = fminf(mind[2 * k], d0);
            float m1 = fminf(mind[2 * k + 1], d1);
            mind[2 * k] = m0;
            mind[2 * k + 1] = m1;
            vloc = fmaxf(vloc, fmaxf(m0, m1));
        }
        unsigned wmax = __reduce_max_sync(0xffffffffu, __float_as_uint(vloc));
        float wmaxf = __uint_as_float(wmax);
        unsigned idxl = 0xffffffffu;
#pragma unroll
        for (int j = FPS_P - 1; j >= 0; j--)
            if (mind[j] == wmaxf) idxl = t * FPS_P + j;
        unsigned widx = __reduce_min_sync(0xffffffffu, idxl);

        const int par = (it & 1) << 4;
        if (lane == 0) { wv[par + warp] = wmax; wi[par + warp] = widx; }
        __syncthreads();

        unsigned bvv = wv[par + (lane & 15)];
        unsigned bii = wi[par + (lane & 15)];
        unsigned vmax = __reduce_max_sync(0xffffffffu, bvv);
        unsigned bi   = __reduce_min_sync(0xffffffffu,
                                          (bvv == vmax) ? bii : 0xffffffffu);

        qx = sx[bi]; qy = sy[bi]; qz = sz[bi];
        if (t == 0) {
            out[it * 3 + 0] = qx;
            out[it * 3 + 1] = qy;
            out[it * 3 + 2] = qz;
        }
    }
}

// ==================================================================
// Kernel 2: ball query (unchanged)
// ==================================================================
__global__ void __launch_bounds__(256)
ballquery_kernel(const float* __restrict__ xyz, const float* __restrict__ newxyz)
{
    const int gw   = (blockIdx.x * blockDim.x + threadIdx.x) >> 5;
    const int lane = threadIdx.x & 31;
    if (gw >= BB * NPOINT) return;
    const int b = gw >> 10;
    const float* bx = xyz + (size_t)b * NN * 3;
    const float cx = newxyz[gw * 3 + 0];
    const float cy = newxyz[gw * 3 + 1];
    const float cz = newxyz[gw * 3 + 2];
    int* out = g_gidx + gw * NSAMPLE;
    const float R2 = (float)0.04;

    int cnt = 0, firstIdx = 0;
    for (int base = 0; base < NN; base += 32) {
        const int i = base + lane;
        float dx = __fsub_rn(bx[i * 3 + 0], cx);
        float dy = __fsub_rn(bx[i * 3 + 1], cy);
        float dz = __fsub_rn(bx[i * 3 + 2], cz);
        float d  = __fadd_rn(__fadd_rn(__fmul_rn(dx, dx), __fmul_rn(dy, dy)),
                             __fmul_rn(dz, dz));
        bool in = d < R2;
        unsigned mask = __ballot_sync(0xffffffffu, in);
        if (mask) {
            if (cnt == 0) firstIdx = base + (__ffs(mask) - 1);
            if (in) {
                int slot = cnt + __popc(mask & ((1u << lane) - 1u));
                if (slot < NSAMPLE) out[slot] = i;
            }
            cnt += __popc(mask);
            if (cnt >= NSAMPLE) break;
        }
    }
    if (lane >= cnt) out[lane] = (cnt > 0) ? firstIdx : 0;
}

// ==================================================================
// Kernel 3: MLP, thread = ONE sample, 16-channel passes (acc[8]=16
// regs -> NO spills), weights stored once and read as warp-broadcast
// LDS.128 (conflict-free), per-thread ping-pong activation rows
// (pitch 67 in / 65 out, both coprime with 32 -> conflict-free).
// Lanes touch only their own rows => ZERO sync after weight load.
// Warp = one group (lanes = 32 samples); maxpool = REDUX per channel.
// Per-channel accumulation order (ascending c, fma chain) identical
// to all previous bit-exact versions.
// ==================================================================
#define MLP_T   256
#define PIN     67      // input-row pitch  (67 % 32 = 3)
#define POUT    65      // output-row pitch (65 % 32 = 1)

__device__ __forceinline__ void pass16(const float* __restrict__ wb, int wstride,
                                       const float* __restrict__ xin, int cin,
                                       unsigned long long acc[8])
{
#pragma unroll
    for (int i = 0; i < 8; i++) acc[i] = 0ull;
#pragma unroll 1
    for (int c = 0; c < cin; c++) {
        float xv = xin[c];
        unsigned long long x2 = pk2(xv, xv);
        const ulonglong2* wr = (const ulonglong2*)(wb + c * wstride);
        ulonglong2 wa = wr[0], wbq = wr[1];
        acc[0] = fma2_(x2, wa.x,  acc[0]);
        acc[1] = fma2_(x2, wa.y,  acc[1]);
        acc[2] = fma2_(x2, wbq.x, acc[2]);
        acc[3] = fma2_(x2, wbq.y, acc[3]);
        const ulonglong2* wr2 = (const ulonglong2*)(wb + c * wstride + 8);
        ulonglong2 wc = wr2[0], wd = wr2[1];
        acc[4] = fma2_(x2, wc.x, acc[4]);
        acc[5] = fma2_(x2, wc.y, acc[5]);
        acc[6] = fma2_(x2, wd.x, acc[6]);
        acc[7] = fma2_(x2, wd.y, acc[7]);
    }
}

__global__ void __launch_bounds__(MLP_T, 1)
mlp_kernel(const float* __restrict__ xyz, const float* __restrict__ feat,
           const float* __restrict__ w0, const float* __restrict__ s0g, const float* __restrict__ b0g,
           const float* __restrict__ w1, const float* __restrict__ s1g, const float* __restrict__ b1g,
           const float* __restrict__ w2, const float* __restrict__ s2g, const float* __restrict__ b2g,
           const float* __restrict__ newxyz, float* __restrict__ outfeat)
{
    extern __shared__ float sm[];
    float* w0s = sm;                    // [c][64]  67*64
    float* w1s = w0s + CIN0 * 64;       // [c][64]  64*64
    float* w2s = w1s + 64 * 64;         // [c][128] 64*128
    float* sc0 = w2s + 64 * 128;
    float* bi0 = sc0 + 64;
    float* sc1 = bi0 + 64;
    float* bi1 = sc1 + 64;
    float* sc2 = bi1 + 64;              // 128
    float* bi2 = sc2 + 128;             // 128
    float* xA  = bi2 + 128;             // 256 * PIN
    float* xB  = xA + MLP_T * PIN;      // 256 * POUT

    const int t = threadIdx.x;

    // weight staging (transposed [c][o]); read later as broadcast
    for (int i = t; i < CIN0 * 64; i += MLP_T) { int o = i & 63,  c = i >> 6; w0s[i] = w0[o * CIN0 + c]; }
    for (int i = t; i < 64 * 64;  i += MLP_T) { int o = i & 63,  c = i >> 6; w1s[i] = w1[o * 64 + c]; }
    for (int i = t; i < 64 * 128; i += MLP_T) { int o = i & 127, c = i >> 7; w2s[i] = w2[o * 64 + c]; }
    if (t < 64)  { sc0[t] = s0g[t]; bi0[t] = b0g[t]; sc1[t] = s1g[t]; bi1[t] = b1g[t]; }
    if (t < 128) { sc2[t] = s2g[t]; bi2[t] = b2g[t]; }
    __syncthreads();

    const int sid  = blockIdx.x * MLP_T + t;   // global sample id
    const int gi   = sid >> 5;                 // group id (warp == group)
    const int n    = sid & 31;                 // sample within group == lane
    const int b    = gi >> 10;
    const int sidx = gi & 1023;

    float* rowA = xA + t * PIN;
    float* rowB = xB + t * POUT;

    // ---- gather: this thread's sample only ----
    {
        const int pi = g_gidx[gi * NSAMPLE + n];
        const float cx = newxyz[gi * 3 + 0];
        const float cy = newxyz[gi * 3 + 1];
        const float cz = newxyz[gi * 3 + 2];
        const float* prow = xyz + ((size_t)b * NN + pi) * 3;
        rowA[0] = __fsub_rn(prow[0], cx);
        rowA[1] = __fsub_rn(prow[1], cy);
        rowA[2] = __fsub_rn(prow[2], cz);
        const float4* frow = (const float4*)(feat + ((size_t)b * NN + pi) * CFEAT);
#pragma unroll
        for (int k = 0; k < 16; k++) {
            float4 f = frow[k];
            rowA[3 + 4 * k + 0] = f.x;
            rowA[3 + 4 * k + 1] = f.y;
            rowA[3 + 4 * k + 2] = f.z;
            rowA[3 + 4 * k + 3] = f.w;
        }
    }

    unsigned long long acc[8];

    // ---- layer 0: 67 -> 64, rowA -> rowB ----
#pragma unroll 1
    for (int p = 0; p < 4; p++) {
        pass16(w0s + p * 16, 64, rowA, CIN0, acc);
#pragma unroll
        for (int u = 0; u < 8; u++) {
            float a0, a1;
            upk2(acc[u], a0, a1);
            int oc = p * 16 + 2 * u;
            float v0 = __fadd_rn(__fmul_rn(a0, sc0[oc]),     bi0[oc]);
            float v1 = __fadd_rn(__fmul_rn(a1, sc0[oc + 1]), bi0[oc + 1]);
            rowB[oc]     = fmaxf(v0, 0.0f);
            rowB[oc + 1] = fmaxf(v1, 0.0f);
        }
    }

    // ---- layer 1: 64 -> 64, rowB -> rowA ----
#pragma unroll 1
    for (int p = 0; p < 4; p++) {
        pass16(w1s + p * 16, 64, rowB, 64, acc);
#pragma unroll
        for (int u = 0; u < 8; u++) {
            float a0, a1;
            upk2(acc[u], a0, a1);
            int oc = p * 16 + 2 * u;
            float v0 = __fadd_rn(__fmul_rn(a0, sc1[oc]),     bi1[oc]);
            float v1 = __fadd_rn(__fmul_rn(a1, sc1[oc + 1]), bi1[oc + 1]);
            rowA[oc]     = fmaxf(v0, 0.0f);
            rowA[oc + 1] = fmaxf(v1, 0.0f);
        }
    }

    // ---- layer 2: 64 -> 128, rowA -> maxpool(REDUX over 32 lanes) ----
    const size_t outbase = (size_t)b * 128 * NPOINT + sidx;
#pragma unroll 1
    for (int p = 0; p < 8; p++) {
        pass16(w2s + p * 16, 128, rowA, 64, acc);
#pragma unroll
        for (int u = 0; u < 8; u++) {
            float a0, a1;
            upk2(acc[u], a0, a1);
            int oc = p * 16 + 2 * u;
            float v0 = __fadd_rn(__fmul_rn(a0, sc2[oc]),     bi2[oc]);
            float v1 = __fadd_rn(__fmul_rn(a1, sc2[oc + 1]), bi2[oc + 1]);
            float r0 = (v0 > 0.0f) ? v0 : 0.0f;   // never -0.0
            float r1 = (v1 > 0.0f) ? v1 : 0.0f;
            unsigned m0 = __reduce_max_sync(0xffffffffu, __float_as_uint(r0));
            unsigned m1 = __reduce_max_sync(0xffffffffu, __float_as_uint(r1));
            if (n == 2 * u)
                outfeat[outbase + (size_t)oc * NPOINT] = __uint_as_float(m0);
            if (n == 2 * u + 1)
                outfeat[outbase + (size_t)(oc + 1) * NPOINT] = __uint_as_float(m1);
        }
    }
}

// ==================================================================
// launch
// ==================================================================
extern "C" void kernel_launch(void* const* d_in, const int* in_sizes, int n_in,
                              void* d_out, int out_size)
{
    (void)in_sizes; (void)n_in; (void)out_size;
    const float* xyz  = (const float*)d_in[0];
    const float* feat = (const float*)d_in[1];
    const float* w0 = (const float*)d_in[2];
    const float* s0 = (const float*)d_in[3];
    const float* b0 = (const float*)d_in[4];
    const float* w1 = (const float*)d_in[5];
    const float* s1 = (const float*)d_in[6];
    const float* b1 = (const float*)d_in[7];
    const float* w2 = (const float*)d_in[8];
    const float* s2 = (const float*)d_in[9];
    const float* b2 = (const float*)d_in[10];

    float* out     = (float*)d_out;
    float* newxyz  = out;                            // (B, NPOINT, 3)
    float* outfeat = out + (size_t)BB * NPOINT * 3;  // (B, 128, NPOINT)

    const int FPS_SMEM = (3 * NN + 64) * 4 + 16;
    const int MLP_SMEM = (CIN0 * 64 + 64 * 64 + 64 * 128 + 512 +
                          MLP_T * PIN + MLP_T * POUT) * 4;   // 203,520 B
    cudaFuncSetAttribute(fps_kernel, cudaFuncAttributeMaxDynamicSharedMemorySize, FPS_SMEM);
    cudaFuncSetAttribute(mlp_kernel, cudaFuncAttributeMaxDynamicSharedMemorySize, MLP_SMEM);

    fps_kernel<<<BB, FPS_T, FPS_SMEM>>>(xyz, newxyz);
    ballquery_kernel<<<(BB * NPOINT * 32) / 256, 256>>>(xyz, newxyz);
    mlp_kernel<<<(BB * NPOINT * NSAMPLE) / MLP_T, MLP_T, MLP_SMEM>>>(
        xyz, feat, w0, s0, b0, w1, s1, b1, w2, s2, b2, newxyz, outfeat);
}

// round 10
// speedup vs baseline: 2.8978x; 1.1935x over previous
#include <cuda_runtime.h>
#include <cstdint>

#define BB       8
#define NN       8192
#define NPOINT   1024
#define NSAMPLE  32
#define CFEAT    64
#define CIN0     67      // 3 + 64

#define MLP_BLOCKS 148
#define NWARPS_TOT (MLP_BLOCKS * 16)

// ------------------------------------------------------------------
// scratch (no allocations allowed)
// ------------------------------------------------------------------
__device__ int g_gidx[BB * NPOINT * NSAMPLE];
__device__ unsigned g_mlp_ctr = NWARPS_TOT;   // reset by ballquery each run

// ------------------------------------------------------------------
// packed f32x2 helpers (Blackwell sm_103a) — add/mul/fma only
// ------------------------------------------------------------------
__device__ __forceinline__ unsigned long long pk2(float lo, float hi) {
    unsigned long long r;
    asm("mov.b64 %0, {%1, %2};" : "=l"(r) : "f"(lo), "f"(hi));
    return r;
}
__device__ __forceinline__ void upk2(unsigned long long v, float& lo, float& hi) {
    asm("mov.b64 {%0, %1}, %2;" : "=f"(lo), "=f"(hi) : "l"(v));
}
__device__ __forceinline__ unsigned long long add2_(unsigned long long a, unsigned long long b) {
    unsigned long long r;
    asm("add.rn.f32x2 %0, %1, %2;" : "=l"(r) : "l"(a), "l"(b));
    return r;
}
__device__ __forceinline__ unsigned long long mul2_(unsigned long long a, unsigned long long b) {
    unsigned long long r;
    asm("mul.rn.f32x2 %0, %1, %2;" : "=l"(r) : "l"(a), "l"(b));
    return r;
}
__device__ __forceinline__ unsigned long long fma2_(unsigned long long a, unsigned long long b,
                                                    unsigned long long c) {
    unsigned long long r;
    asm("fma.rn.f32x2 %0, %1, %2, %3;" : "=l"(r) : "l"(a), "l"(b), "l"(c));
    return r;
}

// ==================================================================
// Kernel 1: FPS (R6/R8 proven config — measured 510 µs three times).
// 512 thr/block, 1 block/batch, single barrier per iter,
// double-buffered partials. Bit-exact vs reference.
// ==================================================================
#define FPS_T 512
#define FPS_P (NN / FPS_T)   // 16

__global__ void __launch_bounds__(FPS_T, 1)
fps_kernel(const float* __restrict__ xyz, float* __restrict__ newxyz)
{
    extern __shared__ float sm[];
    float* sx = sm;
    float* sy = sm + NN;
    float* sz = sm + 2 * NN;
    unsigned* wv = (unsigned*)(sm + 3 * NN);   // [2][16]
    unsigned* wi = wv + 32;                    // [2][16]

    const int b = blockIdx.x;
    const float* bx = xyz + (size_t)b * NN * 3;
    float* out = newxyz + (size_t)b * NPOINT * 3;
    const int t = threadIdx.x;
    const int lane = t & 31;
    const int warp = t >> 5;

    unsigned long long px2[FPS_P / 2], py2[FPS_P / 2], pz2[FPS_P / 2];
    float mind[FPS_P];
#pragma unroll
    for (int k = 0; k < FPS_P / 2; k++) {
        int i0 = t * FPS_P + 2 * k;
        int i1 = i0 + 1;
        float x0 = bx[i0 * 3 + 0], y0 = bx[i0 * 3 + 1], z0 = bx[i0 * 3 + 2];
        float x1 = bx[i1 * 3 + 0], y1 = bx[i1 * 3 + 1], z1 = bx[i1 * 3 + 2];
        px2[k] = pk2(x0, x1); py2[k] = pk2(y0, y1); pz2[k] = pk2(z0, z1);
        sx[i0] = x0; sy[i0] = y0; sz[i0] = z0;
        sx[i1] = x1; sy[i1] = y1; sz[i1] = z1;
        mind[2 * k] = 1e10f; mind[2 * k + 1] = 1e10f;
    }
    __syncthreads();

    float qx = sx[0], qy = sy[0], qz = sz[0];
    if (t == 0) { out[0] = qx; out[1] = qy; out[2] = qz; }

    for (int it = 1; it < NPOINT; it++) {
        const unsigned long long nqx = pk2(-qx, -qx);
        const unsigned long long nqy = pk2(-qy, -qy);
        const unsigned long long nqz = pk2(-qz, -qz);
        float vloc = -1.0f;
#pragma unroll
        for (int k = 0; k < FPS_P / 2; k++) {
            unsigned long long dx = add2_(px2[k], nqx);
            unsigned long long dy = add2_(py2[k], nqy);
            unsigned long long dz = add2_(pz2[k], nqz);
            unsigned long long d2 = add2_(add2_(mul2_(dx, dx), mul2_(dy, dy)),
                                          mul2_(dz, dz));
            float d0, d1;
            upk2(d2, d0, d1);
            float m0 = fminf(mind[2 * k], d0);
            float m1 = fminf(mind[2 * k + 1], d1);
            mind[2 * k] = m0;
            mind[2 * k + 1] = m1;
            vloc = fmaxf(vloc, fmaxf(m0, m1));
        }
        unsigned wmax = __reduce_max_sync(0xffffffffu, __float_as_uint(vloc));
        float wmaxf = __uint_as_float(wmax);
        unsigned idxl = 0xffffffffu;
#pragma unroll
        for (int j = FPS_P - 1; j >= 0; j--)
            if (mind[j] == wmaxf) idxl = t * FPS_P + j;
        unsigned widx = __reduce_min_sync(0xffffffffu, idxl);

        const int par = (it & 1) << 4;
        if (lane == 0) { wv[par + warp] = wmax; wi[par + warp] = widx; }
        __syncthreads();

        unsigned bvv = wv[par + (lane & 15)];
        unsigned bii = wi[par + (lane & 15)];
        unsigned vmax = __reduce_max_sync(0xffffffffu, bvv);
        unsigned bi   = __reduce_min_sync(0xffffffffu,
                                          (bvv == vmax) ? bii : 0xffffffffu);

        qx = sx[bi]; qy = sy[bi]; qz = sz[bi];
        if (t == 0) {
            out[it * 3 + 0] = qx;
            out[it * 3 + 1] = qy;
            out[it * 3 + 2] = qz;
        }
    }
}

// ==================================================================
// Kernel 2: ball query (unchanged) + resets the MLP steal counter
// ==================================================================
__global__ void __launch_bounds__(256)
ballquery_kernel(const float* __restrict__ xyz, const float* __restrict__ newxyz)
{
    if (blockIdx.x == 0 && threadIdx.x == 0) g_mlp_ctr = NWARPS_TOT;

    const int gw   = (blockIdx.x * blockDim.x + threadIdx.x) >> 5;
    const int lane = threadIdx.x & 31;
    if (gw >= BB * NPOINT) return;
    const int b = gw >> 10;
    const float* bx = xyz + (size_t)b * NN * 3;
    const float cx = newxyz[gw * 3 + 0];
    const float cy = newxyz[gw * 3 + 1];
    const float cz = newxyz[gw * 3 + 2];
    int* out = g_gidx + gw * NSAMPLE;
    const float R2 = (float)0.04;

    int cnt = 0, firstIdx = 0;
    for (int base = 0; base < NN; base += 32) {
        const int i = base + lane;
        float dx = __fsub_rn(bx[i * 3 + 0], cx);
        float dy = __fsub_rn(bx[i * 3 + 1], cy);
        float dz = __fsub_rn(bx[i * 3 + 2], cz);
        float d  = __fadd_rn(__fadd_rn(__fmul_rn(dx, dx), __fmul_rn(dy, dy)),
                             __fmul_rn(dz, dz));
        bool in = d < R2;
        unsigned mask = __ballot_sync(0xffffffffu, in);
        if (mask) {
            if (cnt == 0) firstIdx = base + (__ffs(mask) - 1);
            if (in) {
                int slot = cnt + __popc(mask & ((1u << lane) - 1u));
                if (slot < NSAMPLE) out[slot] = i;
            }
            cnt += __popc(mask);
            if (cnt >= NSAMPLE) break;
        }
    }
    if (lane >= cnt) out[lane] = (cnt > 0) ? firstIdx : 0;
}

// ==================================================================
// Kernel 3: MLP — R6 mapping (warp = group, thread = 4 samples x 16
// channels, slice-major skewed weights) made PERSISTENT with
// per-warp work stealing (atomic counter; next group id prefetched
// before processing the current one). 148 blocks x 16 warps.
// ==================================================================
#define MLP_T   512
#define RPITCH  67               // 67 % 32 = 3 -> 8 samples hit 8 banks
#define W0SL    (CIN0 * 16 + 4)  // 1076 floats per slice (skewed)
#define W1SL    (64 * 16 + 4)    // 1028
#define W2SL    (64 * 16 + 4)    // 1028

__global__ void __launch_bounds__(MLP_T, 1)
mlp_kernel(const float* __restrict__ xyz, const float* __restrict__ feat,
           const float* __restrict__ w0, const float* __restrict__ s0g, const float* __restrict__ b0g,
           const float* __restrict__ w1, const float* __restrict__ s1g, const float* __restrict__ b1g,
           const float* __restrict__ w2, const float* __restrict__ s2g, const float* __restrict__ b2g,
           const float* __restrict__ newxyz, float* __restrict__ outfeat)
{
    extern __shared__ float sm[];
    float* w0v = sm;                    // 4 slices x W0SL
    float* w1v = w0v + 4 * W0SL;        // 4 slices x W1SL
    float* w2v = w1v + 4 * W1SL;        // 8 slices x W2SL
    float* sc0 = w2v + 8 * W2SL;
    float* bi0 = sc0 + 64;
    float* sc1 = bi0 + 64;
    float* bi1 = sc1 + 64;
    float* sc2 = bi1 + 64;              // 128
    float* bi2 = sc2 + 128;             // 128
    float* xr  = bi2 + 128;             // 16 * 32 * RPITCH

    const int t = threadIdx.x;
    const int lane = t & 31;
    const int g = t >> 5;               // warp within block
    const int q = lane & 7;             // sample quad id (samples 4q..4q+3)
    const int s = lane >> 3;            // channel-slice id (0..3)

    // ---- weight load: slice-major [slice][c][16] with +4 skew ----
    for (int i = t; i < 4 * CIN0 * 16; i += MLP_T) {
        int sl = i / (CIN0 * 16), r = i - sl * (CIN0 * 16);
        int c = r >> 4, k = r & 15;
        w0v[sl * W0SL + r] = w0[(sl * 16 + k) * CIN0 + c];
    }
    for (int i = t; i < 4 * 64 * 16; i += MLP_T) {
        int sl = i >> 10, r = i & 1023;
        int c = r >> 4, k = r & 15;
        w1v[sl * W1SL + r] = w1[(sl * 16 + k) * 64 + c];
    }
    for (int i = t; i < 8 * 64 * 16; i += MLP_T) {
        int sl = i >> 10, r = i & 1023;
        int c = r >> 4, k = r & 15;
        w2v[sl * W2SL + r] = w2[(sl * 16 + k) * 64 + c];
    }
    if (t < 64)  { sc0[t] = s0g[t]; bi0[t] = b0g[t]; sc1[t] = s1g[t]; bi1[t] = b1g[t]; }
    if (t < 128) { sc2[t] = s2g[t]; bi2[t] = b2g[t]; }
    __syncthreads();

    float* xg = xr + g * 32 * RPITCH;
    const int q2 = (q >> 2) & 1, q1 = (q >> 1) & 1, q0 = q & 1;

    int gi = blockIdx.x * 16 + g;       // initial group = global warp id

    while (gi < BB * NPOINT) {
        // prefetch next group id (latency hidden behind this group)
        unsigned nxt;
        if (lane == 0) nxt = atomicAdd(&g_mlp_ctr, 1u);
        nxt = __shfl_sync(0xffffffffu, nxt, 0);

        const int b    = gi >> 10;
        const int sidx = gi & 1023;

        // ---- gather: this thread fills rows of its 4 samples ----
        {
            const float cx = newxyz[gi * 3 + 0];
            const float cy = newxyz[gi * 3 + 1];
            const float cz = newxyz[gi * 3 + 2];
#pragma unroll
            for (int j = 0; j < 4; j++) {
                const int n = 4 * q + j;
                const int pi = g_gidx[gi * NSAMPLE + n];
                float* row = xg + n * RPITCH;
                const float* prow = xyz + ((size_t)b * NN + pi) * 3;
                row[0] = __fsub_rn(prow[0], cx);
                row[1] = __fsub_rn(prow[1], cy);
                row[2] = __fsub_rn(prow[2], cz);
                const float4* frow = (const float4*)(feat + ((size_t)b * NN + pi) * CFEAT);
#pragma unroll
                for (int k = 0; k < 16; k++) {
                    float4 f = frow[k];
                    row[3 + 4 * k + 0] = f.x;
                    row[3 + 4 * k + 1] = f.y;
                    row[3 + 4 * k + 2] = f.z;
                    row[3 + 4 * k + 3] = f.w;
                }
            }
        }
        __syncwarp();

        unsigned long long acc[32];
        const int chb = s * 16;

        // ---- layer 0: 67 -> 64 ----
        {
            const float* wb = w0v + s * W0SL;
#pragma unroll
            for (int i = 0; i < 32; i++) acc[i] = 0ull;
#pragma unroll 1
            for (int c = 0; c < CIN0; c++) {
                const ulonglong2* wr = (const ulonglong2*)(wb + c * 16);
                ulonglong2 wA = wr[0], wB = wr[1];
                unsigned long long x0 = pk2(xg[(4 * q + 0) * RPITCH + c], xg[(4 * q + 0) * RPITCH + c]);
                unsigned long long x1 = pk2(xg[(4 * q + 1) * RPITCH + c], xg[(4 * q + 1) * RPITCH + c]);
                unsigned long long x2 = pk2(xg[(4 * q + 2) * RPITCH + c], xg[(4 * q + 2) * RPITCH + c]);
                unsigned long long x3 = pk2(xg[(4 * q + 3) * RPITCH + c], xg[(4 * q + 3) * RPITCH + c]);
                acc[0]  = fma2_(x0, wA.x, acc[0]);  acc[1]  = fma2_(x0, wA.y, acc[1]);
                acc[2]  = fma2_(x0, wB.x, acc[2]);  acc[3]  = fma2_(x0, wB.y, acc[3]);
                acc[8]  = fma2_(x1, wA.x, acc[8]);  acc[9]  = fma2_(x1, wA.y, acc[9]);
                acc[10] = fma2_(x1, wB.x, acc[10]); acc[11] = fma2_(x1, wB.y, acc[11]);
                acc[16] = fma2_(x2, wA.x, acc[16]); acc[17] = fma2_(x2, wA.y, acc[17]);
                acc[18] = fma2_(x2, wB.x, acc[18]); acc[19] = fma2_(x2, wB.y, acc[19]);
                acc[24] = fma2_(x3, wA.x, acc[24]); acc[25] = fma2_(x3, wA.y, acc[25]);
                acc[26] = fma2_(x3, wB.x, acc[26]); acc[27] = fma2_(x3, wB.y, acc[27]);
                const ulonglong2* wr2 = (const ulonglong2*)(wb + c * 16 + 8);
                ulonglong2 wC = wr2[0], wD = wr2[1];
                acc[4]  = fma2_(x0, wC.x, acc[4]);  acc[5]  = fma2_(x0, wC.y, acc[5]);
                acc[6]  = fma2_(x0, wD.x, acc[6]);  acc[7]  = fma2_(x0, wD.y, acc[7]);
                acc[12] = fma2_(x1, wC.x, acc[12]); acc[13] = fma2_(x1, wC.y, acc[13]);
                acc[14] = fma2_(x1, wD.x, acc[14]); acc[15] = fma2_(x1, wD.y, acc[15]);
                acc[20] = fma2_(x2, wC.x, acc[20]); acc[21] = fma2_(x2, wC.y, acc[21]);
                acc[22] = fma2_(x2, wD.x, acc[22]); acc[23] = fma2_(x2, wD.y, acc[23]);
                acc[28] = fma2_(x3, wC.x, acc[28]); acc[29] = fma2_(x3, wC.y, acc[29]);
                acc[30] = fma2_(x3, wD.x, acc[30]); acc[31] = fma2_(x3, wD.y, acc[31]);
            }
            __syncwarp();
#pragma unroll
            for (int j = 0; j < 4; j++) {
                float* row = xg + (4 * q + j) * RPITCH;
#pragma unroll
                for (int u = 0; u < 8; u++) {
                    float a0, a1;
                    upk2(acc[j * 8 + u], a0, a1);
                    int oc = chb + 2 * u;
                    float v0 = __fadd_rn(__fmul_rn(a0, sc0[oc]),     bi0[oc]);
                    float v1 = __fadd_rn(__fmul_rn(a1, sc0[oc + 1]), bi0[oc + 1]);
                    row[oc]     = fmaxf(v0, 0.0f);
                    row[oc + 1] = fmaxf(v1, 0.0f);
                }
            }
            __syncwarp();
        }

        // ---- layer 1: 64 -> 64 ----
        {
            const float* wb = w1v + s * W1SL;
#pragma unroll
            for (int i = 0; i < 32; i++) acc[i] = 0ull;
#pragma unroll 1
            for (int c = 0; c < 64; c++) {
                const ulonglong2* wr = (const ulonglong2*)(wb + c * 16);
                ulonglong2 wA = wr[0], wB = wr[1];
                unsigned long long x0 = pk2(xg[(4 * q + 0) * RPITCH + c], xg[(4 * q + 0) * RPITCH + c]);
                unsigned long long x1 = pk2(xg[(4 * q + 1) * RPITCH + c], xg[(4 * q + 1) * RPITCH + c]);
                unsigned long long x2 = pk2(xg[(4 * q + 2) * RPITCH + c], xg[(4 * q + 2) * RPITCH + c]);
                unsigned long long x3 = pk2(xg[(4 * q + 3) * RPITCH + c], xg[(4 * q + 3) * RPITCH + c]);
                acc[0]  = fma2_(x0, wA.x, acc[0]);  acc[1]  = fma2_(x0, wA.y, acc[1]);
                acc[2]  = fma2_(x0, wB.x, acc[2]);  acc[3]  = fma2_(x0, wB.y, acc[3]);
                acc[8]  = fma2_(x1, wA.x, acc[8]);  acc[9]  = fma2_(x1, wA.y, acc[9]);
                acc[10] = fma2_(x1, wB.x, acc[10]); acc[11] = fma2_(x1, wB.y, acc[11]);
                acc[16] = fma2_(x2, wA.x, acc[16]); acc[17] = fma2_(x2, wA.y, acc[17]);
                acc[18] = fma2_(x2, wB.x, acc[18]); acc[19] = fma2_(x2, wB.y, acc[19]);
                acc[24] = fma2_(x3, wA.x, acc[24]); acc[25] = fma2_(x3, wA.y, acc[25]);
                acc[26] = fma2_(x3, wB.x, acc[26]); acc[27] = fma2_(x3, wB.y, acc[27]);
                const ulonglong2* wr2 = (const ulonglong2*)(wb + c * 16 + 8);
                ulonglong2 wC = wr2[0], wD = wr2[1];
                acc[4]  = fma2_(x0, wC.x, acc[4]);  acc[5]  = fma2_(x0, wC.y, acc[5]);
                acc[6]  = fma2_(x0, wD.x, acc[6]);  acc[7]  = fma2_(x0, wD.y, acc[7]);
                acc[12] = fma2_(x1, wC.x, acc[12]); acc[13] = fma2_(x1, wC.y, acc[13]);
                acc[14] = fma2_(x1, wD.x, acc[14]); acc[15] = fma2_(x1, wD.y, acc[15]);
                acc[20] = fma2_(x2, wC.x, acc[20]); acc[21] = fma2_(x2, wC.y, acc[21]);
                acc[22] = fma2_(x2, wD.x, acc[22]); acc[23] = fma2_(x2, wD.y, acc[23]);
                acc[28] = fma2_(x3, wC.x, acc[28]); acc[29] = fma2_(x3, wC.y, acc[29]);
                acc[30] = fma2_(x3, wD.x, acc[30]); acc[31] = fma2_(x3, wD.y, acc[31]);
            }
            __syncwarp();
#pragma unroll
            for (int j = 0; j < 4; j++) {
                float* row = xg + (4 * q + j) * RPITCH;
#pragma unroll
                for (int u = 0; u < 8; u++) {
                    float a0, a1;
                    upk2(acc[j * 8 + u], a0, a1);
                    int oc = chb + 2 * u;
                    float v0 = __fadd_rn(__fmul_rn(a0, sc1[oc]),     bi1[oc]);
                    float v1 = __fadd_rn(__fmul_rn(a1, sc1[oc + 1]), bi1[oc + 1]);
                    row[oc]     = fmaxf(v0, 0.0f);
                    row[oc + 1] = fmaxf(v1, 0.0f);
                }
            }
            __syncwarp();
        }

        // ---- layer 2: 64 -> 128 in 2 rounds; reduce-scatter maxpool ----
        const size_t outbase = (size_t)b * 128 * NPOINT + sidx;
#pragma unroll 1
        for (int r = 0; r < 2; r++) {
            const int p = s + 4 * r;              // slice 0..7
            const float* wb = w2v + p * W2SL;
#pragma unroll
            for (int i = 0; i < 32; i++) acc[i] = 0ull;
#pragma unroll 1
            for (int c = 0; c < 64; c++) {
                const ulonglong2* wr = (const ulonglong2*)(wb + c * 16);
                ulonglong2 wA = wr[0], wB = wr[1];
                unsigned long long x0 = pk2(xg[(4 * q + 0) * RPITCH + c], xg[(4 * q + 0) * RPITCH + c]);
                unsigned long long x1 = pk2(xg[(4 * q + 1) * RPITCH + c], xg[(4 * q + 1) * RPITCH + c]);
                unsigned long long x2 = pk2(xg[(4 * q + 2) * RPITCH + c], xg[(4 * q + 2) * RPITCH + c]);
                unsigned long long x3 = pk2(xg[(4 * q + 3) * RPITCH + c], xg[(4 * q + 3) * RPITCH + c]);
                acc[0]  = fma2_(x0, wA.x, acc[0]);  acc[1]  = fma2_(x0, wA.y, acc[1]);
                acc[2]  = fma2_(x0, wB.x, acc[2]);  acc[3]  = fma2_(x0, wB.y, acc[3]);
                acc[8]  = fma2_(x1, wA.x, acc[8]);  acc[9]  = fma2_(x1, wA.y, acc[9]);
                acc[10] = fma2_(x1, wB.x, acc[10]); acc[11] = fma2_(x1, wB.y, acc[11]);
                acc[16] = fma2_(x2, wA.x, acc[16]); acc[17] = fma2_(x2, wA.y, acc[17]);
                acc[18] = fma2_(x2, wB.x, acc[18]); acc[19] = fma2_(x2, wB.y, acc[19]);
                acc[24] = fma2_(x3, wA.x, acc[24]); acc[25] = fma2_(x3, wA.y, acc[25]);
                acc[26] = fma2_(x3, wB.x, acc[26]); acc[27] = fma2_(x3, wB.y, acc[27]);
                const ulonglong2* wr2 = (const ulonglong2*)(wb + c * 16 + 8);
                ulonglong2 wC = wr2[0], wD = wr2[1];
                acc[4]  = fma2_(x0, wC.x, acc[4]);  acc[5]  = fma2_(x0, wC.y, acc[5]);
                acc[6]  = fma2_(x0, wD.x, acc[6]);  acc[7]  = fma2_(x0, wD.y, acc[7]);
                acc[12] = fma2_(x1, wC.x, acc[12]); acc[13] = fma2_(x1, wC.y, acc[13]);
                acc[14] = fma2_(x1, wD.x, acc[14]); acc[15] = fma2_(x1, wD.y, acc[15]);
                acc[20] = fma2_(x2, wC.x, acc[20]); acc[21] = fma2_(x2, wC.y, acc[21]);
                acc[22] = fma2_(x2, wD.x, acc[22]); acc[23] = fma2_(x2, wD.y, acc[23]);
                acc[28] = fma2_(x3, wC.x, acc[28]); acc[29] = fma2_(x3, wC.y, acc[29]);
                acc[30] = fma2_(x3, wD.x, acc[30]); acc[31] = fma2_(x3, wD.y, acc[31]);
            }
            float vm[16];
#pragma unroll
            for (int u = 0; u < 8; u++) {
                int oc = p * 16 + 2 * u;
                float scA = sc2[oc], biA = bi2[oc], scB = sc2[oc + 1], biB = bi2[oc + 1];
                float m0 = 0.0f, m1 = 0.0f;   // relu floor
#pragma unroll
                for (int j = 0; j < 4; j++) {
                    float a0, a1;
                    upk2(acc[j * 8 + u], a0, a1);
                    float v0 = __fadd_rn(__fmul_rn(a0, scA), biA);
                    float v1 = __fadd_rn(__fmul_rn(a1, scB), biB);
                    m0 = fmaxf(m0, fmaxf(v0, 0.0f));
                    m1 = fmaxf(m1, fmaxf(v1, 0.0f));
                }
                vm[2 * u] = m0; vm[2 * u + 1] = m1;
            }
            float B8[8];
#pragma unroll
            for (int i = 0; i < 8; i++) {
                float snd = q2 ? vm[i] : vm[8 + i];
                float got = __shfl_xor_sync(0xffffffffu, snd, 4);
                float kp  = q2 ? vm[8 + i] : vm[i];
                B8[i] = fmaxf(kp, got);
            }
            float C4[4];
#pragma unroll
            for (int i = 0; i < 4; i++) {
                float snd = q1 ? B8[i] : B8[4 + i];
                float got = __shfl_xor_sync(0xffffffffu, snd, 2);
                float kp  = q1 ? B8[4 + i] : B8[i];
                C4[i] = fmaxf(kp, got);
            }
            float D0, D1;
            {
                float snd = q0 ? C4[0] : C4[2];
                float got = __shfl_xor_sync(0xffffffffu, snd, 1);
                float kp  = q0 ? C4[2] : C4[0];
                D0 = fmaxf(kp, got);
                snd = q0 ? C4[1] : C4[3];
                got = __shfl_xor_sync(0xffffffffu, snd, 1);
                kp  = q0 ? C4[3] : C4[1];
                D1 = fmaxf(kp, got);
            }
            const int ch = p * 16 + 2 * q;
            outfeat[outbase + (size_t)ch * NPOINT]       = D0;
            outfeat[outbase + (size_t)(ch + 1) * NPOINT] = D1;
        }

        gi = (int)nxt;
    }
}

// ==================================================================
// launch
// ==================================================================
extern "C" void kernel_launch(void* const* d_in, const int* in_sizes, int n_in,
                              void* d_out, int out_size)
{
    (void)in_sizes; (void)n_in; (void)out_size;
    const float* xyz  = (const float*)d_in[0];
    const float* feat = (const float*)d_in[1];
    const float* w0 = (const float*)d_in[2];
    const float* s0 = (const float*)d_in[3];
    const float* b0 = (const float*)d_in[4];
    const float* w1 = (const float*)d_in[5];
    const float* s1 = (const float*)d_in[6];
    const float* b1 = (const float*)d_in[7];
    const float* w2 = (const float*)d_in[8];
    const float* s2 = (const float*)d_in[9];
    const float* b2 = (const float*)d_in[10];

    float* out     = (float*)d_out;
    float* newxyz  = out;                            // (B, NPOINT, 3)
    float* outfeat = out + (size_t)BB * NPOINT * 3;  // (B, 128, NPOINT)

    const int FPS_SMEM = (3 * NN + 64) * 4 + 16;
    const int MLP_SMEM = (4 * W0SL + 4 * W1SL + 8 * W2SL + 512 +
                          16 * 32 * RPITCH) * 4;
    cudaFuncSetAttribute(fps_kernel, cudaFuncAttributeMaxDynamicSharedMemorySize, FPS_SMEM);
    cudaFuncSetAttribute(mlp_kernel, cudaFuncAttributeMaxDynamicSharedMemorySize, MLP_SMEM);

    fps_kernel<<<BB, FPS_T, FPS_SMEM>>>(xyz, newxyz);
    ballquery_kernel<<<(BB * NPOINT * 32) / 256, 256>>>(xyz, newxyz);
    mlp_kernel<<<MLP_BLOCKS, MLP_T, MLP_SMEM>>>(
        xyz, feat, w0, s0, b0, w1, s1, b1, w2, s2, b2, newxyz, outfeat);
}

// round 11
// speedup vs baseline: 3.2111x; 1.1081x over previous
#include <cuda_runtime.h>
#include <cstdint>

#define BB       8
#define NN       8192
#define NPOINT   1024
#define NSAMPLE  32
#define CFEAT    64
#define CIN0     67      // 3 + 64

#define MLP_BLOCKS 140                  // blocks 8..147 of the fused grid
#define NWARPS_TOT (MLP_BLOCKS * 16)    // 2240 consumer warps

// ------------------------------------------------------------------
// scratch (no allocations allowed)
// ------------------------------------------------------------------
__device__ unsigned g_prog[BB * 32];    // per-batch FPS progress, 128B padded
__device__ unsigned g_mlp_ctr;          // work-steal counter (reset each run)

// ------------------------------------------------------------------
// packed f32x2 helpers (Blackwell sm_103a) — add/mul/fma only
// ------------------------------------------------------------------
__device__ __forceinline__ unsigned long long pk2(float lo, float hi) {
    unsigned long long r;
    asm("mov.b64 %0, {%1, %2};" : "=l"(r) : "f"(lo), "f"(hi));
    return r;
}
__device__ __forceinline__ void upk2(unsigned long long v, float& lo, float& hi) {
    asm("mov.b64 {%0, %1}, %2;" : "=f"(lo), "=f"(hi) : "l"(v));
}
__device__ __forceinline__ unsigned long long add2_(unsigned long long a, unsigned long long b) {
    unsigned long long r;
    asm("add.rn.f32x2 %0, %1, %2;" : "=l"(r) : "l"(a), "l"(b));
    return r;
}
__device__ __forceinline__ unsigned long long mul2_(unsigned long long a, unsigned long long b) {
    unsigned long long r;
    asm("mul.rn.f32x2 %0, %1, %2;" : "=l"(r) : "l"(a), "l"(b));
    return r;
}
__device__ __forceinline__ unsigned long long fma2_(unsigned long long a, unsigned long long b,
                                                    unsigned long long c) {
    unsigned long long r;
    asm("fma.rn.f32x2 %0, %1, %2, %3;" : "=l"(r) : "l"(a), "l"(b), "l"(c));
    return r;
}
__device__ __forceinline__ unsigned ld_acq32(const unsigned* p) {
    unsigned v;
    asm volatile("ld.acquire.gpu.b32 %0, [%1];" : "=r"(v) : "l"(p) : "memory");
    return v;
}
__device__ __forceinline__ void st_rel32(unsigned* p, unsigned v) {
    asm volatile("st.release.gpu.b32 [%0], %1;" :: "l"(p), "r"(v) : "memory");
}

// ==================================================================
// Kernel 0: reset progress + steal counter (runs before fused kernel;
// required because graph replays would otherwise see stale g_prog
// and read the poisoned output buffer).
// ==================================================================
__global__ void resetk()
{
    if (threadIdx.x < BB) g_prog[threadIdx.x * 32] = 0u;
    if (threadIdx.x == 0) g_mlp_ctr = NWARPS_TOT;
}

// ==================================================================
// Fused kernel: blocks 0..7 = FPS producers (proven R6 config +
// per-iteration release of progress); blocks 8..147 = persistent
// MLP consumer warps (steal s-major units, acquire-poll progress,
// in-warp ball query, R10 MLP body).
// All 148 blocks are co-resident (1/SM at ~206KB smem) -> no deadlock.
// ==================================================================
#define FPS_T 512
#define FPS_P (NN / FPS_T)   // 16
#define MLP_T   512
#define RPITCH  67               // 67 % 32 = 3 -> 8 samples hit 8 banks
#define W0SL    (CIN0 * 16 + 4)  // 1076 floats per slice (skewed)
#define W1SL    (64 * 16 + 4)    // 1028
#define W2SL    (64 * 16 + 4)    // 1028

__global__ void __launch_bounds__(512, 1)
fused_kernel(const float* __restrict__ xyz, const float* __restrict__ feat,
             const float* __restrict__ w0, const float* __restrict__ s0g, const float* __restrict__ b0g,
             const float* __restrict__ w1, const float* __restrict__ s1g, const float* __restrict__ b1g,
             const float* __restrict__ w2, const float* __restrict__ s2g, const float* __restrict__ b2g,
             float* __restrict__ newxyz, float* __restrict__ outfeat)
{
    extern __shared__ float sm[];

    if (blockIdx.x < BB) {
        // ================= FPS producer =================
        float* sx = sm;
        float* sy = sm + NN;
        float* sz = sm + 2 * NN;
        unsigned* wv = (unsigned*)(sm + 3 * NN);   // [2][16]
        unsigned* wi = wv + 32;                    // [2][16]

        const int b = blockIdx.x;
        const float* bx = xyz + (size_t)b * NN * 3;
        float* out = newxyz + (size_t)b * NPOINT * 3;
        unsigned* prog = &g_prog[b * 32];
        const int t = threadIdx.x;
        const int lane = t & 31;
        const int warp = t >> 5;

        unsigned long long px2[FPS_P / 2], py2[FPS_P / 2], pz2[FPS_P / 2];
        float mind[FPS_P];
#pragma unroll
        for (int k = 0; k < FPS_P / 2; k++) {
            int i0 = t * FPS_P + 2 * k;
            int i1 = i0 + 1;
            float x0 = bx[i0 * 3 + 0], y0 = bx[i0 * 3 + 1], z0 = bx[i0 * 3 + 2];
            float x1 = bx[i1 * 3 + 0], y1 = bx[i1 * 3 + 1], z1 = bx[i1 * 3 + 2];
            px2[k] = pk2(x0, x1); py2[k] = pk2(y0, y1); pz2[k] = pk2(z0, z1);
            sx[i0] = x0; sy[i0] = y0; sz[i0] = z0;
            sx[i1] = x1; sy[i1] = y1; sz[i1] = z1;
            mind[2 * k] = 1e10f; mind[2 * k + 1] = 1e10f;
        }
        __syncthreads();

        float qx = sx[0], qy = sy[0], qz = sz[0];
        if (t == 0) {
            out[0] = qx; out[1] = qy; out[2] = qz;
            st_rel32(prog, 1u);
        }

        for (int it = 1; it < NPOINT; it++) {
            const unsigned long long nqx = pk2(-qx, -qx);
            const unsigned long long nqy = pk2(-qy, -qy);
            const unsigned long long nqz = pk2(-qz, -qz);
            float vloc = -1.0f;
#pragma unroll
            for (int k = 0; k < FPS_P / 2; k++) {
                unsigned long long dx = add2_(px2[k], nqx);
                unsigned long long dy = add2_(py2[k], nqy);
                unsigned long long dz = add2_(pz2[k], nqz);
                unsigned long long d2 = add2_(add2_(mul2_(dx, dx), mul2_(dy, dy)),
                                              mul2_(dz, dz));
                float d0, d1;
                upk2(d2, d0, d1);
                float m0 = fminf(mind[2 * k], d0);
                float m1 = fminf(mind[2 * k + 1], d1);
                mind[2 * k] = m0;
                mind[2 * k + 1] = m1;
                vloc = fmaxf(vloc, fmaxf(m0, m1));
            }
            unsigned wmax = __reduce_max_sync(0xffffffffu, __float_as_uint(vloc));
            float wmaxf = __uint_as_float(wmax);
            unsigned idxl = 0xffffffffu;
#pragma unroll
            for (int j = FPS_P - 1; j >= 0; j--)
                if (mind[j] == wmaxf) idxl = t * FPS_P + j;
            unsigned widx = __reduce_min_sync(0xffffffffu, idxl);

            const int par = (it & 1) << 4;
            if (lane == 0) { wv[par + warp] = wmax; wi[par + warp] = widx; }
            __syncthreads();

            unsigned bvv = wv[par + (lane & 15)];
            unsigned bii = wi[par + (lane & 15)];
            unsigned vmax = __reduce_max_sync(0xffffffffu, bvv);
            unsigned bi   = __reduce_min_sync(0xffffffffu,
                                              (bvv == vmax) ? bii : 0xffffffffu);

            qx = sx[bi]; qy = sy[bi]; qz = sz[bi];
            if (t == 0) {
                out[it * 3 + 0] = qx;
                out[it * 3 + 1] = qy;
                out[it * 3 + 2] = qz;
                st_rel32(prog, (unsigned)it + 1u);
            }
        }
        return;
    }

    // ================= MLP consumer =================
    float* w0v = sm;                    // 4 slices x W0SL
    float* w1v = w0v + 4 * W0SL;        // 4 slices x W1SL
    float* w2v = w1v + 4 * W1SL;        // 8 slices x W2SL
    float* sc0 = w2v + 8 * W2SL;
    float* bi0 = sc0 + 64;
    float* sc1 = bi0 + 64;
    float* bi1 = sc1 + 64;
    float* sc2 = bi1 + 64;              // 128
    float* bi2 = sc2 + 128;             // 128
    float* xr  = bi2 + 128;             // 16 * 32 * RPITCH

    const int t = threadIdx.x;
    const int lane = t & 31;
    const int g = t >> 5;               // warp within block
    const int q = lane & 7;             // sample quad id (samples 4q..4q+3)
    const int s = lane >> 3;            // channel-slice id (0..3)

    // ---- weight load: slice-major [slice][c][16] with +4 skew ----
    for (int i = t; i < 4 * CIN0 * 16; i += MLP_T) {
        int sl = i / (CIN0 * 16), r = i - sl * (CIN0 * 16);
        int c = r >> 4, k = r & 15;
        w0v[sl * W0SL + r] = w0[(sl * 16 + k) * CIN0 + c];
    }
    for (int i = t; i < 4 * 64 * 16; i += MLP_T) {
        int sl = i >> 10, r = i & 1023;
        int c = r >> 4, k = r & 15;
        w1v[sl * W1SL + r] = w1[(sl * 16 + k) * 64 + c];
    }
    for (int i = t; i < 8 * 64 * 16; i += MLP_T) {
        int sl = i >> 10, r = i & 1023;
        int c = r >> 4, k = r & 15;
        w2v[sl * W2SL + r] = w2[(sl * 16 + k) * 64 + c];
    }
    if (t < 64)  { sc0[t] = s0g[t]; bi0[t] = b0g[t]; sc1[t] = s1g[t]; bi1[t] = b1g[t]; }
    if (t < 128) { sc2[t] = s2g[t]; bi2[t] = b2g[t]; }
    __syncthreads();

    float* xg = xr + g * 32 * RPITCH;
    int* idxbuf = (int*)xg;             // 32 ints, used before gather overwrites
    const int q2 = (q >> 2) & 1, q1 = (q >> 1) & 1, q0 = q & 1;

    unsigned u = (blockIdx.x - BB) * 16 + g;   // initial unit = global warp id

    while (u < BB * NPOINT) {
        // prefetch next steal (latency hidden behind this unit)
        unsigned nxt;
        if (lane == 0) nxt = atomicAdd(&g_mlp_ctr, 1u);
        nxt = __shfl_sync(0xffffffffu, nxt, 0);

        const int sidx = (int)(u >> 3);       // s-major readiness order
        const int b    = (int)(u & 7);
        const int gi   = b * NPOINT + sidx;

        // ---- wait for FPS(b) to publish center sidx ----
        {
            const unsigned* pp = &g_prog[b * 32];
            unsigned pv = ld_acq32(pp);
            while (pv <= (unsigned)sidx) { __nanosleep(64); pv = ld_acq32(pp); }
        }

        const float cx = newxyz[gi * 3 + 0];
        const float cy = newxyz[gi * 3 + 1];
        const float cz = newxyz[gi * 3 + 2];

        // ---- in-warp ball query (bit-exact mask arithmetic) ----
        int myidx;
        {
            const float* bx = xyz + (size_t)b * NN * 3;
            const float R2 = (float)0.04;
            int cnt = 0, firstIdx = 0;
            for (int base = 0; base < NN; base += 32) {
                const int i = base + lane;
                float dx = __fsub_rn(bx[i * 3 + 0], cx);
                float dy = __fsub_rn(bx[i * 3 + 1], cy);
                float dz = __fsub_rn(bx[i * 3 + 2], cz);
                float d  = __fadd_rn(__fadd_rn(__fmul_rn(dx, dx), __fmul_rn(dy, dy)),
                                     __fmul_rn(dz, dz));
                bool in = d < R2;
                unsigned mask = __ballot_sync(0xffffffffu, in);
                if (mask) {
                    if (cnt == 0) firstIdx = base + (__ffs(mask) - 1);
                    if (in) {
                        int slot = cnt + __popc(mask & ((1u << lane) - 1u));
                        if (slot < NSAMPLE) idxbuf[slot] = i;
                    }
                    cnt += __popc(mask);
                    if (cnt >= NSAMPLE) break;
                }
            }
            __syncwarp();
            myidx = (lane < cnt) ? idxbuf[lane] : ((cnt > 0) ? firstIdx : 0);
            __syncwarp();   // all reads done before gather overwrites idxbuf
        }

        // ---- gather: this thread fills rows of its 4 samples ----
#pragma unroll
        for (int j = 0; j < 4; j++) {
            const int n = 4 * q + j;
            const int pi = __shfl_sync(0xffffffffu, myidx, n);
            float* row = xg + n * RPITCH;
            const float* prow = xyz + ((size_t)b * NN + pi) * 3;
            row[0] = __fsub_rn(prow[0], cx);
            row[1] = __fsub_rn(prow[1], cy);
            row[2] = __fsub_rn(prow[2], cz);
            const float4* frow = (const float4*)(feat + ((size_t)b * NN + pi) * CFEAT);
#pragma unroll
            for (int k = 0; k < 16; k++) {
                float4 f = frow[k];
                row[3 + 4 * k + 0] = f.x;
                row[3 + 4 * k + 1] = f.y;
                row[3 + 4 * k + 2] = f.z;
                row[3 + 4 * k + 3] = f.w;
            }
        }
        __syncwarp();

        unsigned long long acc[32];
        const int chb = s * 16;

        // ---- layer 0: 67 -> 64 ----
        {
            const float* wb = w0v + s * W0SL;
#pragma unroll
            for (int i = 0; i < 32; i++) acc[i] = 0ull;
#pragma unroll 1
            for (int c = 0; c < CIN0; c++) {
                const ulonglong2* wr = (const ulonglong2*)(wb + c * 16);
                ulonglong2 wA = wr[0], wB = wr[1];
                unsigned long long x0 = pk2(xg[(4 * q + 0) * RPITCH + c], xg[(4 * q + 0) * RPITCH + c]);
                unsigned long long x1 = pk2(xg[(4 * q + 1) * RPITCH + c], xg[(4 * q + 1) * RPITCH + c]);
                unsigned long long x2 = pk2(xg[(4 * q + 2) * RPITCH + c], xg[(4 * q + 2) * RPITCH + c]);
                unsigned long long x3 = pk2(xg[(4 * q + 3) * RPITCH + c], xg[(4 * q + 3) * RPITCH + c]);
                acc[0]  = fma2_(x0, wA.x, acc[0]);  acc[1]  = fma2_(x0, wA.y, acc[1]);
                acc[2]  = fma2_(x0, wB.x, acc[2]);  acc[3]  = fma2_(x0, wB.y, acc[3]);
                acc[8]  = fma2_(x1, wA.x, acc[8]);  acc[9]  = fma2_(x1, wA.y, acc[9]);
                acc[10] = fma2_(x1, wB.x, acc[10]); acc[11] = fma2_(x1, wB.y, acc[11]);
                acc[16] = fma2_(x2, wA.x, acc[16]); acc[17] = fma2_(x2, wA.y, acc[17]);
                acc[18] = fma2_(x2, wB.x, acc[18]); acc[19] = fma2_(x2, wB.y, acc[19]);
                acc[24] = fma2_(x3, wA.x, acc[24]); acc[25] = fma2_(x3, wA.y, acc[25]);
                acc[26] = fma2_(x3, wB.x, acc[26]); acc[27] = fma2_(x3, wB.y, acc[27]);
                const ulonglong2* wr2 = (const ulonglong2*)(wb + c * 16 + 8);
                ulonglong2 wC = wr2[0], wD = wr2[1];
                acc[4]  = fma2_(x0, wC.x, acc[4]);  acc[5]  = fma2_(x0, wC.y, acc[5]);
                acc[6]  = fma2_(x0, wD.x, acc[6]);  acc[7]  = fma2_(x0, wD.y, acc[7]);
                acc[12] = fma2_(x1, wC.x, acc[12]); acc[13] = fma2_(x1, wC.y, acc[13]);
                acc[14] = fma2_(x1, wD.x, acc[14]); acc[15] = fma2_(x1, wD.y, acc[15]);
                acc[20] = fma2_(x2, wC.x, acc[20]); acc[21] = fma2_(x2, wC.y, acc[21]);
                acc[22] = fma2_(x2, wD.x, acc[22]); acc[23] = fma2_(x2, wD.y, acc[23]);
                acc[28] = fma2_(x3, wC.x, acc[28]); acc[29] = fma2_(x3, wC.y, acc[29]);
                acc[30] = fma2_(x3, wD.x, acc[30]); acc[31] = fma2_(x3, wD.y, acc[31]);
            }
            __syncwarp();
#pragma unroll
            for (int j = 0; j < 4; j++) {
                float* row = xg + (4 * q + j) * RPITCH;
#pragma unroll
                for (int u2 = 0; u2 < 8; u2++) {
                    float a0, a1;
                    upk2(acc[j * 8 + u2], a0, a1);
                    int oc = chb + 2 * u2;
                    float v0 = __fadd_rn(__fmul_rn(a0, sc0[oc]),     bi0[oc]);
                    float v1 = __fadd_rn(__fmul_rn(a1, sc0[oc + 1]), bi0[oc + 1]);
                    row[oc]     = fmaxf(v0, 0.0f);
                    row[oc + 1] = fmaxf(v1, 0.0f);
                }
            }
            __syncwarp();
        }

        // ---- layer 1: 64 -> 64 ----
        {
            const float* wb = w1v + s * W1SL;
#pragma unroll
            for (int i = 0; i < 32; i++) acc[i] = 0ull;
#pragma unroll 1
            for (int c = 0; c < 64; c++) {
                const ulonglong2* wr = (const ulonglong2*)(wb + c * 16);
                ulonglong2 wA = wr[0], wB = wr[1];
                unsigned long long x0 = pk2(xg[(4 * q + 0) * RPITCH + c], xg[(4 * q + 0) * RPITCH + c]);
                unsigned long long x1 = pk2(xg[(4 * q + 1) * RPITCH + c], xg[(4 * q + 1) * RPITCH + c]);
                unsigned long long x2 = pk2(xg[(4 * q + 2) * RPITCH + c], xg[(4 * q + 2) * RPITCH + c]);
                unsigned long long x3 = pk2(xg[(4 * q + 3) * RPITCH + c], xg[(4 * q + 3) * RPITCH + c]);
                acc[0]  = fma2_(x0, wA.x, acc[0]);  acc[1]  = fma2_(x0, wA.y, acc[1]);
                acc[2]  = fma2_(x0, wB.x, acc[2]);  acc[3]  = fma2_(x0, wB.y, acc[3]);
                acc[8]  = fma2_(x1, wA.x, acc[8]);  acc[9]  = fma2_(x1, wA.y, acc[9]);
                acc[10] = fma2_(x1, wB.x, acc[10]); acc[11] = fma2_(x1, wB.y, acc[11]);
                acc[16] = fma2_(x2, wA.x, acc[16]); acc[17] = fma2_(x2, wA.y, acc[17]);
                acc[18] = fma2_(x2, wB.x, acc[18]); acc[19] = fma2_(x2, wB.y, acc[19]);
                acc[24] = fma2_(x3, wA.x, acc[24]); acc[25] = fma2_(x3, wA.y, acc[25]);
                acc[26] = fma2_(x3, wB.x, acc[26]); acc[27] = fma2_(x3, wB.y, acc[27]);
                const ulonglong2* wr2 = (const ulonglong2*)(wb + c * 16 + 8);
                ulonglong2 wC = wr2[0], wD = wr2[1];
                acc[4]  = fma2_(x0, wC.x, acc[4]);  acc[5]  = fma2_(x0, wC.y, acc[5]);
                acc[6]  = fma2_(x0, wD.x, acc[6]);  acc[7]  = fma2_(x0, wD.y, acc[7]);
                acc[12] = fma2_(x1, wC.x, acc[12]); acc[13] = fma2_(x1, wC.y, acc[13]);
                acc[14] = fma2_(x1, wD.x, acc[14]); acc[15] = fma2_(x1, wD.y, acc[15]);
                acc[20] = fma2_(x2, wC.x, acc[20]); acc[21] = fma2_(x2, wC.y, acc[21]);
                acc[22] = fma2_(x2, wD.x, acc[22]); acc[23] = fma2_(x2, wD.y, acc[23]);
                acc[28] = fma2_(x3, wC.x, acc[28]); acc[29] = fma2_(x3, wC.y, acc[29]);
                acc[30] = fma2_(x3, wD.x, acc[30]); acc[31] = fma2_(x3, wD.y, acc[31]);
            }
            __syncwarp();
#pragma unroll
            for (int j = 0; j < 4; j++) {
                float* row = xg + (4 * q + j) * RPITCH;
#pragma unroll
                for (int u2 = 0; u2 < 8; u2++) {
                    float a0, a1;
                    upk2(acc[j * 8 + u2], a0, a1);
                    int oc = chb + 2 * u2;
                    float v0 = __fadd_rn(__fmul_rn(a0, sc1[oc]),     bi1[oc]);
                    float v1 = __fadd_rn(__fmul_rn(a1, sc1[oc + 1]), bi1[oc + 1]);
                    row[oc]     = fmaxf(v0, 0.0f);
                    row[oc + 1] = fmaxf(v1, 0.0f);
                }
            }
            __syncwarp();
        }

        // ---- layer 2: 64 -> 128 in 2 rounds; reduce-scatter maxpool ----
        const size_t outbase = (size_t)b * 128 * NPOINT + sidx;
#pragma unroll 1
        for (int r = 0; r < 2; r++) {
            const int p = s + 4 * r;              // slice 0..7
            const float* wb = w2v + p * W2SL;
#pragma unroll
            for (int i = 0; i < 32; i++) acc[i] = 0ull;
#pragma unroll 1
            for (int c = 0; c < 64; c++) {
                const ulonglong2* wr = (const ulonglong2*)(wb + c * 16);
                ulonglong2 wA = wr[0], wB = wr[1];
                unsigned long long x0 = pk2(xg[(4 * q + 0) * RPITCH + c], xg[(4 * q + 0) * RPITCH + c]);
                unsigned long long x1 = pk2(xg[(4 * q + 1) * RPITCH + c], xg[(4 * q + 1) * RPITCH + c]);
                unsigned long long x2 = pk2(xg[(4 * q + 2) * RPITCH + c], xg[(4 * q + 2) * RPITCH + c]);
                unsigned long long x3 = pk2(xg[(4 * q + 3) * RPITCH + c], xg[(4 * q + 3) * RPITCH + c]);
                acc[0]  = fma2_(x0, wA.x, acc[0]);  acc[1]  = fma2_(x0, wA.y, acc[1]);
                acc[2]  = fma2_(x0, wB.x, acc[2]);  acc[3]  = fma2_(x0, wB.y, acc[3]);
                acc[8]  = fma2_(x1, wA.x, acc[8]);  acc[9]  = fma2_(x1, wA.y, acc[9]);
                acc[10] = fma2_(x1, wB.x, acc[10]); acc[11] = fma2_(x1, wB.y, acc[11]);
                acc[16] = fma2_(x2, wA.x, acc[16]); acc[17] = fma2_(x2, wA.y, acc[17]);
                acc[18] = fma2_(x2, wB.x, acc[18]); acc[19] = fma2_(x2, wB.y, acc[19]);
                acc[24] = fma2_(x3, wA.x, acc[24]); acc[25] = fma2_(x3, wA.y, acc[25]);
                acc[26] = fma2_(x3, wB.x, acc[26]); acc[27] = fma2_(x3, wB.y, acc[27]);
                const ulonglong2* wr2 = (const ulonglong2*)(wb + c * 16 + 8);
                ulonglong2 wC = wr2[0], wD = wr2[1];
                acc[4]  = fma2_(x0, wC.x, acc[4]);  acc[5]  = fma2_(x0, wC.y, acc[5]);
                acc[6]  = fma2_(x0, wD.x, acc[6]);  acc[7]  = fma2_(x0, wD.y, acc[7]);
                acc[12] = fma2_(x1, wC.x, acc[12]); acc[13] = fma2_(x1, wC.y, acc[13]);
                acc[14] = fma2_(x1, wD.x, acc[14]); acc[15] = fma2_(x1, wD.y, acc[15]);
                acc[20] = fma2_(x2, wC.x, acc[20]); acc[21] = fma2_(x2, wC.y, acc[21]);
                acc[22] = fma2_(x2, wD.x, acc[22]); acc[23] = fma2_(x2, wD.y, acc[23]);
                acc[28] = fma2_(x3, wC.x, acc[28]); acc[29] = fma2_(x3, wC.y, acc[29]);
                acc[30] = fma2_(x3, wD.x, acc[30]); acc[31] = fma2_(x3, wD.y, acc[31]);
            }
            float vm[16];
#pragma unroll
            for (int u2 = 0; u2 < 8; u2++) {
                int oc = p * 16 + 2 * u2;
                float scA = sc2[oc], biA = bi2[oc], scB = sc2[oc + 1], biB = bi2[oc + 1];
                float m0 = 0.0f, m1 = 0.0f;   // relu floor
#pragma unroll
                for (int j = 0; j < 4; j++) {
                    float a0, a1;
                    upk2(acc[j * 8 + u2], a0, a1);
                    float v0 = __fadd_rn(__fmul_rn(a0, scA), biA);
                    float v1 = __fadd_rn(__fmul_rn(a1, scB), biB);
                    m0 = fmaxf(m0, fmaxf(v0, 0.0f));
                    m1 = fmaxf(m1, fmaxf(v1, 0.0f));
                }
                vm[2 * u2] = m0; vm[2 * u2 + 1] = m1;
            }
            float B8[8];
#pragma unroll
            for (int i = 0; i < 8; i++) {
                float snd = q2 ? vm[i] : vm[8 + i];
                float got = __shfl_xor_sync(0xffffffffu, snd, 4);
                float kp  = q2 ? vm[8 + i] : vm[i];
                B8[i] = fmaxf(kp, got);
            }
            float C4[4];
#pragma unroll
            for (int i = 0; i < 4; i++) {
                float snd = q1 ? B8[i] : B8[4 + i];
                float got = __shfl_xor_sync(0xffffffffu, snd, 2);
                float kp  = q1 ? B8[4 + i] : B8[i];
                C4[i] = fmaxf(kp, got);
            }
            float D0, D1;
            {
                float snd = q0 ? C4[0] : C4[2];
                float got = __shfl_xor_sync(0xffffffffu, snd, 1);
                float kp  = q0 ? C4[2] : C4[0];
                D0 = fmaxf(kp, got);
                snd = q0 ? C4[1] : C4[3];
                got = __shfl_xor_sync(0xffffffffu, snd, 1);
                kp  = q0 ? C4[3] : C4[1];
                D1 = fmaxf(kp, got);
            }
            const int ch = p * 16 + 2 * q;
            outfeat[outbase + (size_t)ch * NPOINT]       = D0;
            outfeat[outbase + (size_t)(ch + 1) * NPOINT] = D1;
        }

        u = nxt;
    }
}

// ==================================================================
// launch
// ==================================================================
extern "C" void kernel_launch(void* const* d_in, const int* in_sizes, int n_in,
                              void* d_out, int out_size)
{
    (void)in_sizes; (void)n_in; (void)out_size;
    const float* xyz  = (const float*)d_in[0];
    const float* feat = (const float*)d_in[1];
    const float* w0 = (const float*)d_in[2];
    const float* s0 = (const float*)d_in[3];
    const float* b0 = (const float*)d_in[4];
    const float* w1 = (const float*)d_in[5];
    const float* s1 = (const float*)d_in[6];
    const float* b1 = (const float*)d_in[7];
    const float* w2 = (const float*)d_in[8];
    const float* s2 = (const float*)d_in[9];
    const float* b2 = (const float*)d_in[10];

    float* out     = (float*)d_out;
    float* newxyz  = out;                            // (B, NPOINT, 3)
    float* outfeat = out + (size_t)BB * NPOINT * 3;  // (B, 128, NPOINT)

    // smem = max(FPS layout, MLP layout) = MLP layout
    const int FUSED_SMEM = (4 * W0SL + 4 * W1SL + 8 * W2SL + 512 +
                            16 * 32 * RPITCH) * 4;   // 205,824 B
    cudaFuncSetAttribute(fused_kernel, cudaFuncAttributeMaxDynamicSharedMemorySize,
                         FUSED_SMEM);

    resetk<<<1, 32>>>();
    fused_kernel<<<BB + MLP_BLOCKS, 512, FUSED_SMEM>>>(
        xyz, feat, w0, s0, b0, w1, s1, b1, w2, s2, b2, newxyz, outfeat);
}

// round 12
// speedup vs baseline: 3.7400x; 1.1647x over previous
#include <cuda_runtime.h>
#include <cstdint>

#define BB       8
#define NN       8192
#define NPOINT   1024
#define NSAMPLE  32
#define CFEAT    64
#define CIN0     67      // 3 + 64

#define MLP_BLOCKS 140                  // blocks 8..147 of the fused grid
#define NWARPS_TOT (MLP_BLOCKS * 16)    // 2240 consumer warps

// ------------------------------------------------------------------
// scratch (no allocations allowed)
// ------------------------------------------------------------------
__device__ unsigned g_prog[BB * 32];    // per-batch FPS progress, 128B padded
__device__ unsigned g_mlp_ctr;          // work-steal counter (reset each run)

// ------------------------------------------------------------------
// packed f32x2 helpers (Blackwell sm_103a) — add/mul/fma only
// ------------------------------------------------------------------
__device__ __forceinline__ unsigned long long pk2(float lo, float hi) {
    unsigned long long r;
    asm("mov.b64 %0, {%1, %2};" : "=l"(r) : "f"(lo), "f"(hi));
    return r;
}
__device__ __forceinline__ void upk2(unsigned long long v, float& lo, float& hi) {
    asm("mov.b64 {%0, %1}, %2;" : "=f"(lo), "=f"(hi) : "l"(v));
}
__device__ __forceinline__ unsigned long long add2_(unsigned long long a, unsigned long long b) {
    unsigned long long r;
    asm("add.rn.f32x2 %0, %1, %2;" : "=l"(r) : "l"(a), "l"(b));
    return r;
}
__device__ __forceinline__ unsigned long long mul2_(unsigned long long a, unsigned long long b) {
    unsigned long long r;
    asm("mul.rn.f32x2 %0, %1, %2;" : "=l"(r) : "l"(a), "l"(b));
    return r;
}
__device__ __forceinline__ unsigned long long fma2_(unsigned long long a, unsigned long long b,
                                                    unsigned long long c) {
    unsigned long long r;
    asm("fma.rn.f32x2 %0, %1, %2, %3;" : "=l"(r) : "l"(a), "l"(b), "l"(c));
    return r;
}
__device__ __forceinline__ unsigned ld_acq32(const unsigned* p) {
    unsigned v;
    asm volatile("ld.acquire.gpu.b32 %0, [%1];" : "=r"(v) : "l"(p) : "memory");
    return v;
}
__device__ __forceinline__ void st_rel32(unsigned* p, unsigned v) {
    asm volatile("st.release.gpu.b32 [%0], %1;" :: "l"(p), "r"(v) : "memory");
}

// ==================================================================
// Kernel 0: reset progress + steal counter (graph replays would
// otherwise see stale g_prog and read the poisoned output buffer).
// ==================================================================
__global__ void resetk()
{
    if (threadIdx.x < BB) g_prog[threadIdx.x * 32] = 0u;
    if (threadIdx.x == 0) g_mlp_ctr = NWARPS_TOT;
}

// ==================================================================
// Fused kernel: blocks 0..7 = FPS producers; blocks 8..147 =
// persistent MLP consumer warps. Progress published every 8
// iterations (release fence off the per-iter critical path);
// consumers poll with exponential backoff.
// ==================================================================
#define FPS_T 512
#define FPS_P (NN / FPS_T)   // 16
#define MLP_T   512
#define RPITCH  67               // 67 % 32 = 3 -> 8 samples hit 8 banks
#define W0SL    (CIN0 * 16 + 4)  // 1076 floats per slice (skewed)
#define W1SL    (64 * 16 + 4)    // 1028
#define W2SL    (64 * 16 + 4)    // 1028

__global__ void __launch_bounds__(512, 1)
fused_kernel(const float* __restrict__ xyz, const float* __restrict__ feat,
             const float* __restrict__ w0, const float* __restrict__ s0g, const float* __restrict__ b0g,
             const float* __restrict__ w1, const float* __restrict__ s1g, const float* __restrict__ b1g,
             const float* __restrict__ w2, const float* __restrict__ s2g, const float* __restrict__ b2g,
             float* __restrict__ newxyz, float* __restrict__ outfeat)
{
    extern __shared__ float sm[];

    if (blockIdx.x < BB) {
        // ================= FPS producer =================
        float* sx = sm;
        float* sy = sm + NN;
        float* sz = sm + 2 * NN;
        unsigned* wv = (unsigned*)(sm + 3 * NN);   // [2][16]
        unsigned* wi = wv + 32;                    // [2][16]

        const int b = blockIdx.x;
        const float* bx = xyz + (size_t)b * NN * 3;
        float* out = newxyz + (size_t)b * NPOINT * 3;
        unsigned* prog = &g_prog[b * 32];
        const int t = threadIdx.x;
        const int lane = t & 31;
        const int warp = t >> 5;

        unsigned long long px2[FPS_P / 2], py2[FPS_P / 2], pz2[FPS_P / 2];
        float mind[FPS_P];
#pragma unroll
        for (int k = 0; k < FPS_P / 2; k++) {
            int i0 = t * FPS_P + 2 * k;
            int i1 = i0 + 1;
            float x0 = bx[i0 * 3 + 0], y0 = bx[i0 * 3 + 1], z0 = bx[i0 * 3 + 2];
            float x1 = bx[i1 * 3 + 0], y1 = bx[i1 * 3 + 1], z1 = bx[i1 * 3 + 2];
            px2[k] = pk2(x0, x1); py2[k] = pk2(y0, y1); pz2[k] = pk2(z0, z1);
            sx[i0] = x0; sy[i0] = y0; sz[i0] = z0;
            sx[i1] = x1; sy[i1] = y1; sz[i1] = z1;
            mind[2 * k] = 1e10f; mind[2 * k + 1] = 1e10f;
        }
        __syncthreads();

        float qx = sx[0], qy = sy[0], qz = sz[0];
        if (t == 0) { out[0] = qx; out[1] = qy; out[2] = qz; }

        for (int it = 1; it < NPOINT; it++) {
            const unsigned long long nqx = pk2(-qx, -qx);
            const unsigned long long nqy = pk2(-qy, -qy);
            const unsigned long long nqz = pk2(-qz, -qz);
            float vloc = -1.0f;
#pragma unroll
            for (int k = 0; k < FPS_P / 2; k++) {
                unsigned long long dx = add2_(px2[k], nqx);
                unsigned long long dy = add2_(py2[k], nqy);
                unsigned long long dz = add2_(pz2[k], nqz);
                unsigned long long d2 = add2_(add2_(mul2_(dx, dx), mul2_(dy, dy)),
                                              mul2_(dz, dz));
                float d0, d1;
                upk2(d2, d0, d1);
                float m0 = fminf(mind[2 * k], d0);
                float m1 = fminf(mind[2 * k + 1], d1);
                mind[2 * k] = m0;
                mind[2 * k + 1] = m1;
                vloc = fmaxf(vloc, fmaxf(m0, m1));
            }
            unsigned wmax = __reduce_max_sync(0xffffffffu, __float_as_uint(vloc));
            float wmaxf = __uint_as_float(wmax);
            unsigned idxl = 0xffffffffu;
#pragma unroll
            for (int j = FPS_P - 1; j >= 0; j--)
                if (mind[j] == wmaxf) idxl = t * FPS_P + j;
            unsigned widx = __reduce_min_sync(0xffffffffu, idxl);

            const int par = (it & 1) << 4;
            if (lane == 0) { wv[par + warp] = wmax; wi[par + warp] = widx; }
            __syncthreads();

            unsigned bvv = wv[par + (lane & 15)];
            unsigned bii = wi[par + (lane & 15)];
            unsigned vmax = __reduce_max_sync(0xffffffffu, bvv);
            unsigned bi   = __reduce_min_sync(0xffffffffu,
                                              (bvv == vmax) ? bii : 0xffffffffu);

            qx = sx[bi]; qy = sy[bi]; qz = sz[bi];
            if (t == 0) {
                out[it * 3 + 0] = qx;
                out[it * 3 + 1] = qy;
                out[it * 3 + 2] = qz;
                // batched release: fence cost off the per-iter path
                if ((it & 7) == 7 || it == NPOINT - 1)
                    st_rel32(prog, (unsigned)it + 1u);
            }
        }
        return;
    }

    // ================= MLP consumer =================
    float* w0v = sm;                    // 4 slices x W0SL
    float* w1v = w0v + 4 * W0SL;        // 4 slices x W1SL
    float* w2v = w1v + 4 * W1SL;        // 8 slices x W2SL
    float* sc0 = w2v + 8 * W2SL;
    float* bi0 = sc0 + 64;
    float* sc1 = bi0 + 64;
    float* bi1 = sc1 + 64;
    float* sc2 = bi1 + 64;              // 128
    float* bi2 = sc2 + 128;             // 128
    float* xr  = bi2 + 128;             // 16 * 32 * RPITCH

    const int t = threadIdx.x;
    const int lane = t & 31;
    const int g = t >> 5;               // warp within block
    const int q = lane & 7;             // sample quad id (samples 4q..4q+3)
    const int s = lane >> 3;            // channel-slice id (0..3)

    // ---- weight load: slice-major [slice][c][16] with +4 skew ----
    for (int i = t; i < 4 * CIN0 * 16; i += MLP_T) {
        int sl = i / (CIN0 * 16), r = i - sl * (CIN0 * 16);
        int c = r >> 4, k = r & 15;
        w0v[sl * W0SL + r] = w0[(sl * 16 + k) * CIN0 + c];
    }
    for (int i = t; i < 4 * 64 * 16; i += MLP_T) {
        int sl = i >> 10, r = i & 1023;
        int c = r >> 4, k = r & 15;
        w1v[sl * W1SL + r] = w1[(sl * 16 + k) * 64 + c];
    }
    for (int i = t; i < 8 * 64 * 16; i += MLP_T) {
        int sl = i >> 10, r = i & 1023;
        int c = r >> 4, k = r & 15;
        w2v[sl * W2SL + r] = w2[(sl * 16 + k) * 64 + c];
    }
    if (t < 64)  { sc0[t] = s0g[t]; bi0[t] = b0g[t]; sc1[t] = s1g[t]; bi1[t] = b1g[t]; }
    if (t < 128) { sc2[t] = s2g[t]; bi2[t] = b2g[t]; }
    __syncthreads();

    float* xg = xr + g * 32 * RPITCH;
    int* idxbuf = (int*)xg;             // 32 ints, used before gather overwrites
    const int q2 = (q >> 2) & 1, q1 = (q >> 1) & 1, q0 = q & 1;

    unsigned u = (blockIdx.x - BB) * 16 + g;   // initial unit = global warp id

    while (u < BB * NPOINT) {
        // prefetch next steal (latency hidden behind this unit)
        unsigned nxt;
        if (lane == 0) nxt = atomicAdd(&g_mlp_ctr, 1u);
        nxt = __shfl_sync(0xffffffffu, nxt, 0);

        const int sidx = (int)(u >> 3);       // s-major readiness order
        const int b    = (int)(u & 7);
        const int gi   = b * NPOINT + sidx;

        // ---- wait for FPS(b) to publish center sidx (backoff poll) ----
        {
            const unsigned* pp = &g_prog[b * 32];
            unsigned pv = ld_acq32(pp);
            int slp = 128;
            while (pv <= (unsigned)sidx) {
                __nanosleep(slp);
                if (slp < 1024) slp <<= 1;
                pv = ld_acq32(pp);
            }
        }

        const float cx = newxyz[gi * 3 + 0];
        const float cy = newxyz[gi * 3 + 1];
        const float cz = newxyz[gi * 3 + 2];

        // ---- in-warp ball query (bit-exact mask arithmetic) ----
        int myidx;
        {
            const float* bx = xyz + (size_t)b * NN * 3;
            const float R2 = (float)0.04;
            int cnt = 0, firstIdx = 0;
            for (int base = 0; base < NN; base += 32) {
                const int i = base + lane;
                float dx = __fsub_rn(bx[i * 3 + 0], cx);
                float dy = __fsub_rn(bx[i * 3 + 1], cy);
                float dz = __fsub_rn(bx[i * 3 + 2], cz);
                float d  = __fadd_rn(__fadd_rn(__fmul_rn(dx, dx), __fmul_rn(dy, dy)),
                                     __fmul_rn(dz, dz));
                bool in = d < R2;
                unsigned mask = __ballot_sync(0xffffffffu, in);
                if (mask) {
                    if (cnt == 0) firstIdx = base + (__ffs(mask) - 1);
                    if (in) {
                        int slot = cnt + __popc(mask & ((1u << lane) - 1u));
                        if (slot < NSAMPLE) idxbuf[slot] = i;
                    }
                    cnt += __popc(mask);
                    if (cnt >= NSAMPLE) break;
                }
            }
            __syncwarp();
            myidx = (lane < cnt) ? idxbuf[lane] : ((cnt > 0) ? firstIdx : 0);
            __syncwarp();   // all reads done before gather overwrites idxbuf
        }

        // ---- gather: this thread fills rows of its 4 samples ----
#pragma unroll
        for (int j = 0; j < 4; j++) {
            const int n = 4 * q + j;
            const int pi = __shfl_sync(0xffffffffu, myidx, n);
            float* row = xg + n * RPITCH;
            const float* prow = xyz + ((size_t)b * NN + pi) * 3;
            row[0] = __fsub_rn(prow[0], cx);
            row[1] = __fsub_rn(prow[1], cy);
            row[2] = __fsub_rn(prow[2], cz);
            const float4* frow = (const float4*)(feat + ((size_t)b * NN + pi) * CFEAT);
#pragma unroll
            for (int k = 0; k < 16; k++) {
                float4 f = frow[k];
                row[3 + 4 * k + 0] = f.x;
                row[3 + 4 * k + 1] = f.y;
                row[3 + 4 * k + 2] = f.z;
                row[3 + 4 * k + 3] = f.w;
            }
        }
        __syncwarp();

        unsigned long long acc[32];
        const int chb = s * 16;

        // ---- layer 0: 67 -> 64 ----
        {
            const float* wb = w0v + s * W0SL;
#pragma unroll
            for (int i = 0; i < 32; i++) acc[i] = 0ull;
#pragma unroll 1
            for (int c = 0; c < CIN0; c++) {
                const ulonglong2* wr = (const ulonglong2*)(wb + c * 16);
                ulonglong2 wA = wr[0], wB = wr[1];
                unsigned long long x0 = pk2(xg[(4 * q + 0) * RPITCH + c], xg[(4 * q + 0) * RPITCH + c]);
                unsigned long long x1 = pk2(xg[(4 * q + 1) * RPITCH + c], xg[(4 * q + 1) * RPITCH + c]);
                unsigned long long x2 = pk2(xg[(4 * q + 2) * RPITCH + c], xg[(4 * q + 2) * RPITCH + c]);
                unsigned long long x3 = pk2(xg[(4 * q + 3) * RPITCH + c], xg[(4 * q + 3) * RPITCH + c]);
                acc[0]  = fma2_(x0, wA.x, acc[0]);  acc[1]  = fma2_(x0, wA.y, acc[1]);
                acc[2]  = fma2_(x0, wB.x, acc[2]);  acc[3]  = fma2_(x0, wB.y, acc[3]);
                acc[8]  = fma2_(x1, wA.x, acc[8]);  acc[9]  = fma2_(x1, wA.y, acc[9]);
                acc[10] = fma2_(x1, wB.x, acc[10]); acc[11] = fma2_(x1, wB.y, acc[11]);
                acc[16] = fma2_(x2, wA.x, acc[16]); acc[17] = fma2_(x2, wA.y, acc[17]);
                acc[18] = fma2_(x2, wB.x, acc[18]); acc[19] = fma2_(x2, wB.y, acc[19]);
                acc[24] = fma2_(x3, wA.x, acc[24]); acc[25] = fma2_(x3, wA.y, acc[25]);
                acc[26] = fma2_(x3, wB.x, acc[26]); acc[27] = fma2_(x3, wB.y, acc[27]);
                const ulonglong2* wr2 = (const ulonglong2*)(wb + c * 16 + 8);
                ulonglong2 wC = wr2[0], wD = wr2[1];
                acc[4]  = fma2_(x0, wC.x, acc[4]);  acc[5]  = fma2_(x0, wC.y, acc[5]);
                acc[6]  = fma2_(x0, wD.x, acc[6]);  acc[7]  = fma2_(x0, wD.y, acc[7]);
                acc[12] = fma2_(x1, wC.x, acc[12]); acc[13] = fma2_(x1, wC.y, acc[13]);
                acc[14] = fma2_(x1, wD.x, acc[14]); acc[15] = fma2_(x1, wD.y, acc[15]);
                acc[20] = fma2_(x2, wC.x, acc[20]); acc[21] = fma2_(x2, wC.y, acc[21]);
                acc[22] = fma2_(x2, wD.x, acc[22]); acc[23] = fma2_(x2, wD.y, acc[23]);
                acc[28] = fma2_(x3, wC.x, acc[28]); acc[29] = fma2_(x3, wC.y, acc[29]);
                acc[30] = fma2_(x3, wD.x, acc[30]); acc[31] = fma2_(x3, wD.y, acc[31]);
            }
            __syncwarp();
#pragma unroll
            for (int j = 0; j < 4; j++) {
                float* row = xg + (4 * q + j) * RPITCH;
#pragma unroll
                for (int u2 = 0; u2 < 8; u2++) {
                    float a0, a1;
                    upk2(acc[j * 8 + u2], a0, a1);
                    int oc = chb + 2 * u2;
                    float v0 = __fadd_rn(__fmul_rn(a0, sc0[oc]),     bi0[oc]);
                    float v1 = __fadd_rn(__fmul_rn(a1, sc0[oc + 1]), bi0[oc + 1]);
                    row[oc]     = fmaxf(v0, 0.0f);
                    row[oc + 1] = fmaxf(v1, 0.0f);
                }
            }
            __syncwarp();
        }

        // ---- layer 1: 64 -> 64 ----
        {
            const float* wb = w1v + s * W1SL;
#pragma unroll
            for (int i = 0; i < 32; i++) acc[i] = 0ull;
#pragma unroll 1
            for (int c = 0; c < 64; c++) {
                const ulonglong2* wr = (const ulonglong2*)(wb + c * 16);
                ulonglong2 wA = wr[0], wB = wr[1];
                unsigned long long x0 = pk2(xg[(4 * q + 0) * RPITCH + c], xg[(4 * q + 0) * RPITCH + c]);
                unsigned long long x1 = pk2(xg[(4 * q + 1) * RPITCH + c], xg[(4 * q + 1) * RPITCH + c]);
                unsigned long long x2 = pk2(xg[(4 * q + 2) * RPITCH + c], xg[(4 * q + 2) * RPITCH + c]);
                unsigned long long x3 = pk2(xg[(4 * q + 3) * RPITCH + c], xg[(4 * q + 3) * RPITCH + c]);
                acc[0]  = fma2_(x0, wA.x, acc[0]);  acc[1]  = fma2_(x0, wA.y, acc[1]);
                acc[2]  = fma2_(x0, wB.x, acc[2]);  acc[3]  = fma2_(x0, wB.y, acc[3]);
                acc[8]  = fma2_(x1, wA.x, acc[8]);  acc[9]  = fma2_(x1, wA.y, acc[9]);
                acc[10] = fma2_(x1, wB.x, acc[10]); acc[11] = fma2_(x1, wB.y, acc[11]);
                acc[16] = fma2_(x2, wA.x, acc[16]); acc[17] = fma2_(x2, wA.y, acc[17]);
                acc[18] = fma2_(x2, wB.x, acc[18]); acc[19] = fma2_(x2, wB.y, acc[19]);
                acc[24] = fma2_(x3, wA.x, acc[24]); acc[25] = fma2_(x3, wA.y, acc[25]);
                acc[26] = fma2_(x3, wB.x, acc[26]); acc[27] = fma2_(x3, wB.y, acc[27]);
                const ulonglong2* wr2 = (const ulonglong2*)(wb + c * 16 + 8);
                ulonglong2 wC = wr2[0], wD = wr2[1];
                acc[4]  = fma2_(x0, wC.x, acc[4]);  acc[5]  = fma2_(x0, wC.y, acc[5]);
                acc[6]  = fma2_(x0, wD.x, acc[6]);  acc[7]  = fma2_(x0, wD.y, acc[7]);
                acc[12] = fma2_(x1, wC.x, acc[12]); acc[13] = fma2_(x1, wC.y, acc[13]);
                acc[14] = fma2_(x1, wD.x, acc[14]); acc[15] = fma2_(x1, wD.y, acc[15]);
                acc[20] = fma2_(x2, wC.x, acc[20]); acc[21] = fma2_(x2, wC.y, acc[21]);
                acc[22] = fma2_(x2, wD.x, acc[22]); acc[23] = fma2_(x2, wD.y, acc[23]);
                acc[28] = fma2_(x3, wC.x, acc[28]); acc[29] = fma2_(x3, wC.y, acc[29]);
                acc[30] = fma2_(x3, wD.x, acc[30]); acc[31] = fma2_(x3, wD.y, acc[31]);
            }
            __syncwarp();
#pragma unroll
            for (int j = 0; j < 4; j++) {
                float* row = xg + (4 * q + j) * RPITCH;
#pragma unroll
                for (int u2 = 0; u2 < 8; u2++) {
                    float a0, a1;
                    upk2(acc[j * 8 + u2], a0, a1);
                    int oc = chb + 2 * u2;
                    float v0 = __fadd_rn(__fmul_rn(a0, sc1[oc]),     bi1[oc]);
                    float v1 = __fadd_rn(__fmul_rn(a1, sc1[oc + 1]), bi1[oc + 1]);
                    row[oc]     = fmaxf(v0, 0.0f);
                    row[oc + 1] = fmaxf(v1, 0.0f);
                }
            }
            __syncwarp();
        }

        // ---- layer 2: 64 -> 128 in 2 rounds; reduce-scatter maxpool ----
        const size_t outbase = (size_t)b * 128 * NPOINT + sidx;
#pragma unroll 1
        for (int r = 0; r < 2; r++) {
            const int p = s + 4 * r;              // slice 0..7
            const float* wb = w2v + p * W2SL;
#pragma unroll
            for (int i = 0; i < 32; i++) acc[i] = 0ull;
#pragma unroll 1
            for (int c = 0; c < 64; c++) {
                const ulonglong2* wr = (const ulonglong2*)(wb + c * 16);
                ulonglong2 wA = wr[0], wB = wr[1];
                unsigned long long x0 = pk2(xg[(4 * q + 0) * RPITCH + c], xg[(4 * q + 0) * RPITCH + c]);
                unsigned long long x1 = pk2(xg[(4 * q + 1) * RPITCH + c], xg[(4 * q + 1) * RPITCH + c]);
                unsigned long long x2 = pk2(xg[(4 * q + 2) * RPITCH + c], xg[(4 * q + 2) * RPITCH + c]);
                unsigned long long x3 = pk2(xg[(4 * q + 3) * RPITCH + c], xg[(4 * q + 3) * RPITCH + c]);
                acc[0]  = fma2_(x0, wA.x, acc[0]);  acc[1]  = fma2_(x0, wA.y, acc[1]);
                acc[2]  = fma2_(x0, wB.x, acc[2]);  acc[3]  = fma2_(x0, wB.y, acc[3]);
                acc[8]  = fma2_(x1, wA.x, acc[8]);  acc[9]  = fma2_(x1, wA.y, acc[9]);
                acc[10] = fma2_(x1, wB.x, acc[10]); acc[11] = fma2_(x1, wB.y, acc[11]);
                acc[16] = fma2_(x2, wA.x, acc[16]); acc[17] = fma2_(x2, wA.y, acc[17]);
                acc[18] = fma2_(x2, wB.x, acc[18]); acc[19] = fma2_(x2, wB.y, acc[19]);
                acc[24] = fma2_(x3, wA.x, acc[24]); acc[25] = fma2_(x3, wA.y, acc[25]);
                acc[26] = fma2_(x3, wB.x, acc[26]); acc[27] = fma2_(x3, wB.y, acc[27]);
                const ulonglong2* wr2 = (const ulonglong2*)(wb + c * 16 + 8);
                ulonglong2 wC = wr2[0], wD = wr2[1];
                acc[4]  = fma2_(x0, wC.x, acc[4]);  acc[5]  = fma2_(x0, wC.y, acc[5]);
                acc[6]  = fma2_(x0, wD.x, acc[6]);  acc[7]  = fma2_(x0, wD.y, acc[7]);
                acc[12] = fma2_(x1, wC.x, acc[12]); acc[13] = fma2_(x1, wC.y, acc[13]);
                acc[14] = fma2_(x1, wD.x, acc[14]); acc[15] = fma2_(x1, wD.y, acc[15]);
                acc[20] = fma2_(x2, wC.x, acc[20]); acc[21] = fma2_(x2, wC.y, acc[21]);
                acc[22] = fma2_(x2, wD.x, acc[22]); acc[23] = fma2_(x2, wD.y, acc[23]);
                acc[28] = fma2_(x3, wC.x, acc[28]); acc[29] = fma2_(x3, wC.y, acc[29]);
                acc[30] = fma2_(x3, wD.x, acc[30]); acc[31] = fma2_(x3, wD.y, acc[31]);
            }
            float vm[16];
#pragma unroll
            for (int u2 = 0; u2 < 8; u2++) {
                int oc = p * 16 + 2 * u2;
                float scA = sc2[oc], biA = bi2[oc], scB = sc2[oc + 1], biB = bi2[oc + 1];
                float m0 = 0.0f, m1 = 0.0f;   // relu floor
#pragma unroll
                for (int j = 0; j < 4; j++) {
                    float a0, a1;
                    upk2(acc[j * 8 + u2], a0, a1);
                    float v0 = __fadd_rn(__fmul_rn(a0, scA), biA);
                    float v1 = __fadd_rn(__fmul_rn(a1, scB), biB);
                    m0 = fmaxf(m0, fmaxf(v0, 0.0f));
                    m1 = fmaxf(m1, fmaxf(v1, 0.0f));
                }
                vm[2 * u2] = m0; vm[2 * u2 + 1] = m1;
            }
            float B8[8];
#pragma unroll
            for (int i = 0; i < 8; i++) {
                float snd = q2 ? vm[i] : vm[8 + i];
                float got = __shfl_xor_sync(0xffffffffu, snd, 4);
                float kp  = q2 ? vm[8 + i] : vm[i];
                B8[i] = fmaxf(kp, got);
            }
            float C4[4];
#pragma unroll
            for (int i = 0; i < 4; i++) {
                float snd = q1 ? B8[i] : B8[4 + i];
                float got = __shfl_xor_sync(0xffffffffu, snd, 2);
                float kp  = q1 ? B8[4 + i] : B8[i];
                C4[i] = fmaxf(kp, got);
            }
            float D0, D1;
            {
                float snd = q0 ? C4[0] : C4[2];
                float got = __shfl_xor_sync(0xffffffffu, snd, 1);
                float kp  = q0 ? C4[2] : C4[0];
                D0 = fmaxf(kp, got);
                snd = q0 ? C4[1] : C4[3];
                got = __shfl_xor_sync(0xffffffffu, snd, 1);
                kp  = q0 ? C4[3] : C4[1];
                D1 = fmaxf(kp, got);
            }
            const int ch = p * 16 + 2 * q;
            outfeat[outbase + (size_t)ch * NPOINT]       = D0;
            outfeat[outbase + (size_t)(ch + 1) * NPOINT] = D1;
        }

        u = nxt;
    }
}

// ==================================================================
// launch
// ==================================================================
extern "C" void kernel_launch(void* const* d_in, const int* in_sizes, int n_in,
                              void* d_out, int out_size)
{
    (void)in_sizes; (void)n_in; (void)out_size;
    const float* xyz  = (const float*)d_in[0];
    const float* feat = (const float*)d_in[1];
    const float* w0 = (const float*)d_in[2];
    const float* s0 = (const float*)d_in[3];
    const float* b0 = (const float*)d_in[4];
    const float* w1 = (const float*)d_in[5];
    const float* s1 = (const float*)d_in[6];
    const float* b1 = (const float*)d_in[7];
    const float* w2 = (const float*)d_in[8];
    const float* s2 = (const float*)d_in[9];
    const float* b2 = (const float*)d_in[10];

    float* out     = (float*)d_out;
    float* newxyz  = out;                            // (B, NPOINT, 3)
    float* outfeat = out + (size_t)BB * NPOINT * 3;  // (B, 128, NPOINT)

    const int FUSED_SMEM = (4 * W0SL + 4 * W1SL + 8 * W2SL + 512 +
                            16 * 32 * RPITCH) * 4;   // ~205,824 B
    cudaFuncSetAttribute(fused_kernel, cudaFuncAttributeMaxDynamicSharedMemorySize,
                         FUSED_SMEM);

    resetk<<<1, 32>>>();
    fused_kernel<<<BB + MLP_BLOCKS, 512, FUSED_SMEM>>>(
        xyz, feat, w0, s0, b0, w1, s1, b1, w2, s2, b2, newxyz, outfeat);
}

// round 13
// speedup vs baseline: 3.7677x; 1.0074x over previous
#include <cuda_runtime.h>
#include <cstdint>

#define BB       8
#define NN       8192
#define NPOINT   1024
#define NSAMPLE  32
#define CFEAT    64
#define CIN0     67      // 3 + 64

#define MLP_BLOCKS 140                  // blocks 8..147 of the fused grid
#define NWARPS_TOT (MLP_BLOCKS * 16)    // 2240 consumer warps

// ------------------------------------------------------------------
// scratch (no allocations allowed)
// ------------------------------------------------------------------
__device__ unsigned g_prog[BB * 32];    // per-batch FPS progress, 128B padded
__device__ unsigned g_mlp_ctr;          // work-steal counter (reset each run)

// ------------------------------------------------------------------
// packed f32x2 helpers (Blackwell sm_103a) — add/mul/fma only
// ------------------------------------------------------------------
__device__ __forceinline__ unsigned long long pk2(float lo, float hi) {
    unsigned long long r;
    asm("mov.b64 %0, {%1, %2};" : "=l"(r) : "f"(lo), "f"(hi));
    return r;
}
__device__ __forceinline__ void upk2(unsigned long long v, float& lo, float& hi) {
    asm("mov.b64 {%0, %1}, %2;" : "=f"(lo), "=f"(hi) : "l"(v));
}
__device__ __forceinline__ unsigned long long add2_(unsigned long long a, unsigned long long b) {
    unsigned long long r;
    asm("add.rn.f32x2 %0, %1, %2;" : "=l"(r) : "l"(a), "l"(b));
    return r;
}
__device__ __forceinline__ unsigned long long mul2_(unsigned long long a, unsigned long long b) {
    unsigned long long r;
    asm("mul.rn.f32x2 %0, %1, %2;" : "=l"(r) : "l"(a), "l"(b));
    return r;
}
__device__ __forceinline__ unsigned long long fma2_(unsigned long long a, unsigned long long b,
                                                    unsigned long long c) {
    unsigned long long r;
    asm("fma.rn.f32x2 %0, %1, %2, %3;" : "=l"(r) : "l"(a), "l"(b), "l"(c));
    return r;
}
__device__ __forceinline__ unsigned ld_acq32(const unsigned* p) {
    unsigned v;
    asm volatile("ld.acquire.gpu.b32 %0, [%1];" : "=r"(v) : "l"(p) : "memory");
    return v;
}
__device__ __forceinline__ void st_rel32(unsigned* p, unsigned v) {
    asm volatile("st.release.gpu.b32 [%0], %1;" :: "l"(p), "r"(v) : "memory");
}

// ==================================================================
// Kernel 0: reset progress + steal counter (graph replays would
// otherwise see stale g_prog and read the poisoned output buffer).
// ==================================================================
__global__ void resetk()
{
    if (threadIdx.x < BB) g_prog[threadIdx.x * 32] = 0u;
    if (threadIdx.x == 0) g_mlp_ctr = NWARPS_TOT;
}

// ==================================================================
// Fused kernel: blocks 0..7 = FPS producers; blocks 8..147 =
// persistent MLP consumer warps. Progress published every 8
// iterations; consumers poll with exponential backoff.
// FPS warp argmax: equality scan vs the thread's OWN max (runs in
// parallel with the REDUX), then ballot/ffs/shfl picks the lowest
// lane attaining the warp max — lane order == index order within a
// warp, so first-max-index semantics are preserved exactly.
// ==================================================================
#define FPS_T 512
#define FPS_P (NN / FPS_T)   // 16
#define MLP_T   512
#define RPITCH  67               // 67 % 32 = 3 -> 8 samples hit 8 banks
#define W0SL    (CIN0 * 16 + 4)  // 1076 floats per slice (skewed)
#define W1SL    (64 * 16 + 4)    // 1028
#define W2SL    (64 * 16 + 4)    // 1028

__global__ void __launch_bounds__(512, 1)
fused_kernel(const float* __restrict__ xyz, const float* __restrict__ feat,
             const float* __restrict__ w0, const float* __restrict__ s0g, const float* __restrict__ b0g,
             const float* __restrict__ w1, const float* __restrict__ s1g, const float* __restrict__ b1g,
             const float* __restrict__ w2, const float* __restrict__ s2g, const float* __restrict__ b2g,
             float* __restrict__ newxyz, float* __restrict__ outfeat)
{
    extern __shared__ float sm[];

    if (blockIdx.x < BB) {
        // ================= FPS producer =================
        float* sx = sm;
        float* sy = sm + NN;
        float* sz = sm + 2 * NN;
        unsigned* wv = (unsigned*)(sm + 3 * NN);   // [2][16]
        unsigned* wi = wv + 32;                    // [2][16]

        const int b = blockIdx.x;
        const float* bx = xyz + (size_t)b * NN * 3;
        float* out = newxyz + (size_t)b * NPOINT * 3;
        unsigned* prog = &g_prog[b * 32];
        const int t = threadIdx.x;
        const int lane = t & 31;
        const int warp = t >> 5;

        unsigned long long px2[FPS_P / 2], py2[FPS_P / 2], pz2[FPS_P / 2];
        float mind[FPS_P];
#pragma unroll
        for (int k = 0; k < FPS_P / 2; k++) {
            int i0 = t * FPS_P + 2 * k;
            int i1 = i0 + 1;
            float x0 = bx[i0 * 3 + 0], y0 = bx[i0 * 3 + 1], z0 = bx[i0 * 3 + 2];
            float x1 = bx[i1 * 3 + 0], y1 = bx[i1 * 3 + 1], z1 = bx[i1 * 3 + 2];
            px2[k] = pk2(x0, x1); py2[k] = pk2(y0, y1); pz2[k] = pk2(z0, z1);
            sx[i0] = x0; sy[i0] = y0; sz[i0] = z0;
            sx[i1] = x1; sy[i1] = y1; sz[i1] = z1;
            mind[2 * k] = 1e10f; mind[2 * k + 1] = 1e10f;
        }
        __syncthreads();

        float qx = sx[0], qy = sy[0], qz = sz[0];
        if (t == 0) { out[0] = qx; out[1] = qy; out[2] = qz; }

        for (int it = 1; it < NPOINT; it++) {
            const unsigned long long nqx = pk2(-qx, -qx);
            const unsigned long long nqy = pk2(-qy, -qy);
            const unsigned long long nqz = pk2(-qz, -qz);
            float vloc = -1.0f;
#pragma unroll
            for (int k = 0; k < FPS_P / 2; k++) {
                unsigned long long dx = add2_(px2[k], nqx);
                unsigned long long dy = add2_(py2[k], nqy);
                unsigned long long dz = add2_(pz2[k], nqz);
                unsigned long long d2 = add2_(add2_(mul2_(dx, dx), mul2_(dy, dy)),
                                              mul2_(dz, dz));
                float d0, d1;
                upk2(d2, d0, d1);
                float m0 = fminf(mind[2 * k], d0);
                float m1 = fminf(mind[2 * k + 1], d1);
                mind[2 * k] = m0;
                mind[2 * k + 1] = m1;
                vloc = fmaxf(vloc, fmaxf(m0, m1));
            }
            // first local index attaining the THREAD max (independent of
            // the REDUX below -> overlaps with it)
            unsigned idxl = 0xffffffffu;
#pragma unroll
            for (int j = FPS_P - 1; j >= 0; j--)
                if (mind[j] == vloc) idxl = t * FPS_P + j;

            unsigned vb = __float_as_uint(vloc);
            unsigned wmax = __reduce_max_sync(0xffffffffu, vb);
            // lowest lane attaining wmax holds the lowest index
            unsigned act = __ballot_sync(0xffffffffu, vb == wmax);
            int src = __ffs(act) - 1;
            unsigned widx = __shfl_sync(0xffffffffu, idxl, src);

            const int par = (it & 1) << 4;
            if (lane == 0) { wv[par + warp] = wmax; wi[par + warp] = widx; }
            __syncthreads();

            unsigned bvv = wv[par + (lane & 15)];
            unsigned bii = wi[par + (lane & 15)];
            unsigned vmax = __reduce_max_sync(0xffffffffu, bvv);
            unsigned bi   = __reduce_min_sync(0xffffffffu,
                                              (bvv == vmax) ? bii : 0xffffffffu);

            qx = sx[bi]; qy = sy[bi]; qz = sz[bi];
            if (t == 0) {
                out[it * 3 + 0] = qx;
                out[it * 3 + 1] = qy;
                out[it * 3 + 2] = qz;
                // batched release: fence cost off the per-iter path
                if ((it & 7) == 7 || it == NPOINT - 1)
                    st_rel32(prog, (unsigned)it + 1u);
            }
        }
        return;
    }

    // ================= MLP consumer =================
    float* w0v = sm;                    // 4 slices x W0SL
    float* w1v = w0v + 4 * W0SL;        // 4 slices x W1SL
    float* w2v = w1v + 4 * W1SL;        // 8 slices x W2SL
    float* sc0 = w2v + 8 * W2SL;
    float* bi0 = sc0 + 64;
    float* sc1 = bi0 + 64;
    float* bi1 = sc1 + 64;
    float* sc2 = bi1 + 64;              // 128
    float* bi2 = sc2 + 128;             // 128
    float* xr  = bi2 + 128;             // 16 * 32 * RPITCH

    const int t = threadIdx.x;
    const int lane = t & 31;
    const int g = t >> 5;               // warp within block
    const int q = lane & 7;             // sample quad id (samples 4q..4q+3)
    const int s = lane >> 3;            // channel-slice id (0..3)

    // ---- weight load: slice-major [slice][c][16] with +4 skew ----
    for (int i = t; i < 4 * CIN0 * 16; i += MLP_T) {
        int sl = i / (CIN0 * 16), r = i - sl * (CIN0 * 16);
        int c = r >> 4, k = r & 15;
        w0v[sl * W0SL + r] = w0[(sl * 16 + k) * CIN0 + c];
    }
    for (int i = t; i < 4 * 64 * 16; i += MLP_T) {
        int sl = i >> 10, r = i & 1023;
        int c = r >> 4, k = r & 15;
        w1v[sl * W1SL + r] = w1[(sl * 16 + k) * 64 + c];
    }
    for (int i = t; i < 8 * 64 * 16; i += MLP_T) {
        int sl = i >> 10, r = i & 1023;
        int c = r >> 4, k = r & 15;
        w2v[sl * W2SL + r] = w2[(sl * 16 + k) * 64 + c];
    }
    if (t < 64)  { sc0[t] = s0g[t]; bi0[t] = b0g[t]; sc1[t] = s1g[t]; bi1[t] = b1g[t]; }
    if (t < 128) { sc2[t] = s2g[t]; bi2[t] = b2g[t]; }
    __syncthreads();

    float* xg = xr + g * 32 * RPITCH;
    int* idxbuf = (int*)xg;             // 32 ints, used before gather overwrites
    const int q2 = (q >> 2) & 1, q1 = (q >> 1) & 1, q0 = q & 1;

    unsigned u = (blockIdx.x - BB) * 16 + g;   // initial unit = global warp id

    while (u < BB * NPOINT) {
        // prefetch next steal (latency hidden behind this unit)
        unsigned nxt;
        if (lane == 0) nxt = atomicAdd(&g_mlp_ctr, 1u);
        nxt = __shfl_sync(0xffffffffu, nxt, 0);

        const int sidx = (int)(u >> 3);       // s-major readiness order
        const int b    = (int)(u & 7);
        const int gi   = b * NPOINT + sidx;

        // ---- wait for FPS(b) to publish center sidx (backoff poll) ----
        {
            const unsigned* pp = &g_prog[b * 32];
            unsigned pv = ld_acq32(pp);
            int slp = 128;
            while (pv <= (unsigned)sidx) {
                __nanosleep(slp);
                if (slp < 1024) slp <<= 1;
                pv = ld_acq32(pp);
            }
        }

        const float cx = newxyz[gi * 3 + 0];
        const float cy = newxyz[gi * 3 + 1];
        const float cz = newxyz[gi * 3 + 2];

        // ---- in-warp ball query (bit-exact mask arithmetic) ----
        int myidx;
        {
            const float* bx = xyz + (size_t)b * NN * 3;
            const float R2 = (float)0.04;
            int cnt = 0, firstIdx = 0;
            for (int base = 0; base < NN; base += 32) {
                const int i = base + lane;
                float dx = __fsub_rn(bx[i * 3 + 0], cx);
                float dy = __fsub_rn(bx[i * 3 + 1], cy);
                float dz = __fsub_rn(bx[i * 3 + 2], cz);
                float d  = __fadd_rn(__fadd_rn(__fmul_rn(dx, dx), __fmul_rn(dy, dy)),
                                     __fmul_rn(dz, dz));
                bool in = d < R2;
                unsigned mask = __ballot_sync(0xffffffffu, in);
                if (mask) {
                    if (cnt == 0) firstIdx = base + (__ffs(mask) - 1);
                    if (in) {
                        int slot = cnt + __popc(mask & ((1u << lane) - 1u));
                        if (slot < NSAMPLE) idxbuf[slot] = i;
                    }
                    cnt += __popc(mask);
                    if (cnt >= NSAMPLE) break;
                }
            }
            __syncwarp();
            myidx = (lane < cnt) ? idxbuf[lane] : ((cnt > 0) ? firstIdx : 0);
            __syncwarp();   // all reads done before gather overwrites idxbuf
        }

        // ---- gather: this thread fills rows of its 4 samples ----
#pragma unroll
        for (int j = 0; j < 4; j++) {
            const int n = 4 * q + j;
            const int pi = __shfl_sync(0xffffffffu, myidx, n);
            float* row = xg + n * RPITCH;
            const float* prow = xyz + ((size_t)b * NN + pi) * 3;
            row[0] = __fsub_rn(prow[0], cx);
            row[1] = __fsub_rn(prow[1], cy);
            row[2] = __fsub_rn(prow[2], cz);
            const float4* frow = (const float4*)(feat + ((size_t)b * NN + pi) * CFEAT);
#pragma unroll
            for (int k = 0; k < 16; k++) {
                float4 f = frow[k];
                row[3 + 4 * k + 0] = f.x;
                row[3 + 4 * k + 1] = f.y;
                row[3 + 4 * k + 2] = f.z;
                row[3 + 4 * k + 3] = f.w;
            }
        }
        __syncwarp();

        unsigned long long acc[32];
        const int chb = s * 16;

        // ---- layer 0: 67 -> 64 ----
        {
            const float* wb = w0v + s * W0SL;
#pragma unroll
            for (int i = 0; i < 32; i++) acc[i] = 0ull;
#pragma unroll 1
            for (int c = 0; c < CIN0; c++) {
                const ulonglong2* wr = (const ulonglong2*)(wb + c * 16);
                ulonglong2 wA = wr[0], wB = wr[1];
                unsigned long long x0 = pk2(xg[(4 * q + 0) * RPITCH + c], xg[(4 * q + 0) * RPITCH + c]);
                unsigned long long x1 = pk2(xg[(4 * q + 1) * RPITCH + c], xg[(4 * q + 1) * RPITCH + c]);
                unsigned long long x2 = pk2(xg[(4 * q + 2) * RPITCH + c], xg[(4 * q + 2) * RPITCH + c]);
                unsigned long long x3 = pk2(xg[(4 * q + 3) * RPITCH + c], xg[(4 * q + 3) * RPITCH + c]);
                acc[0]  = fma2_(x0, wA.x, acc[0]);  acc[1]  = fma2_(x0, wA.y, acc[1]);
                acc[2]  = fma2_(x0, wB.x, acc[2]);  acc[3]  = fma2_(x0, wB.y, acc[3]);
                acc[8]  = fma2_(x1, wA.x, acc[8]);  acc[9]  = fma2_(x1, wA.y, acc[9]);
                acc[10] = fma2_(x1, wB.x, acc[10]); acc[11] = fma2_(x1, wB.y, acc[11]);
                acc[16] = fma2_(x2, wA.x, acc[16]); acc[17] = fma2_(x2, wA.y, acc[17]);
                acc[18] = fma2_(x2, wB.x, acc[18]); acc[19] = fma2_(x2, wB.y, acc[19]);
                acc[24] = fma2_(x3, wA.x, acc[24]); acc[25] = fma2_(x3, wA.y, acc[25]);
                acc[26] = fma2_(x3, wB.x, acc[26]); acc[27] = fma2_(x3, wB.y, acc[27]);
                const ulonglong2* wr2 = (const ulonglong2*)(wb + c * 16 + 8);
                ulonglong2 wC = wr2[0], wD = wr2[1];
                acc[4]  = fma2_(x0, wC.x, acc[4]);  acc[5]  = fma2_(x0, wC.y, acc[5]);
                acc[6]  = fma2_(x0, wD.x, acc[6]);  acc[7]  = fma2_(x0, wD.y, acc[7]);
                acc[12] = fma2_(x1, wC.x, acc[12]); acc[13] = fma2_(x1, wC.y, acc[13]);
                acc[14] = fma2_(x1, wD.x, acc[14]); acc[15] = fma2_(x1, wD.y, acc[15]);
                acc[20] = fma2_(x2, wC.x, acc[20]); acc[21] = fma2_(x2, wC.y, acc[21]);
                acc[22] = fma2_(x2, wD.x, acc[22]); acc[23] = fma2_(x2, wD.y, acc[23]);
                acc[28] = fma2_(x3, wC.x, acc[28]); acc[29] = fma2_(x3, wC.y, acc[29]);
                acc[30] = fma2_(x3, wD.x, acc[30]); acc[31] = fma2_(x3, wD.y, acc[31]);
            }
            __syncwarp();
#pragma unroll
            for (int j = 0; j < 4; j++) {
                float* row = xg + (4 * q + j) * RPITCH;
#pragma unroll
                for (int u2 = 0; u2 < 8; u2++) {
                    float a0, a1;
                    upk2(acc[j * 8 + u2], a0, a1);
                    int oc = chb + 2 * u2;
                    float v0 = __fadd_rn(__fmul_rn(a0, sc0[oc]),     bi0[oc]);
                    float v1 = __fadd_rn(__fmul_rn(a1, sc0[oc + 1]), bi0[oc + 1]);
                    row[oc]     = fmaxf(v0, 0.0f);
                    row[oc + 1] = fmaxf(v1, 0.0f);
                }
            }
            __syncwarp();
        }

        // ---- layer 1: 64 -> 64 ----
        {
            const float* wb = w1v + s * W1SL;
#pragma unroll
            for (int i = 0; i < 32; i++) acc[i] = 0ull;
#pragma unroll 1
            for (int c = 0; c < 64; c++) {
                const ulonglong2* wr = (const ulonglong2*)(wb + c * 16);
                ulonglong2 wA = wr[0], wB = wr[1];
                unsigned long long x0 = pk2(xg[(4 * q + 0) * RPITCH + c], xg[(4 * q + 0) * RPITCH + c]);
                unsigned long long x1 = pk2(xg[(4 * q + 1) * RPITCH + c], xg[(4 * q + 1) * RPITCH + c]);
                unsigned long long x2 = pk2(xg[(4 * q + 2) * RPITCH + c], xg[(4 * q + 2) * RPITCH + c]);
                unsigned long long x3 = pk2(xg[(4 * q + 3) * RPITCH + c], xg[(4 * q + 3) * RPITCH + c]);
                acc[0]  = fma2_(x0, wA.x, acc[0]);  acc[1]  = fma2_(x0, wA.y, acc[1]);
                acc[2]  = fma2_(x0, wB.x, acc[2]);  acc[3]  = fma2_(x0, wB.y, acc[3]);
                acc[8]  = fma2_(x1, wA.x, acc[8]);  acc[9]  = fma2_(x1, wA.y, acc[9]);
                acc[10] = fma2_(x1, wB.x, acc[10]); acc[11] = fma2_(x1, wB.y, acc[11]);
                acc[16] = fma2_(x2, wA.x, acc[16]); acc[17] = fma2_(x2, wA.y, acc[17]);
                acc[18] = fma2_(x2, wB.x, acc[18]); acc[19] = fma2_(x2, wB.y, acc[19]);
                acc[24] = fma2_(x3, wA.x, acc[24]); acc[25] = fma2_(x3, wA.y, acc[25]);
                acc[26] = fma2_(x3, wB.x, acc[26]); acc[27] = fma2_(x3, wB.y, acc[27]);
                const ulonglong2* wr2 = (const ulonglong2*)(wb + c * 16 + 8);
                ulonglong2 wC = wr2[0], wD = wr2[1];
                acc[4]  = fma2_(x0, wC.x, acc[4]);  acc[5]  = fma2_(x0, wC.y, acc[5]);
                acc[6]  = fma2_(x0, wD.x, acc[6]);  acc[7]  = fma2_(x0, wD.y, acc[7]);
                acc[12] = fma2_(x1, wC.x, acc[12]); acc[13] = fma2_(x1, wC.y, acc[13]);
                acc[14] = fma2_(x1, wD.x, acc[14]); acc[15] = fma2_(x1, wD.y, acc[15]);
                acc[20] = fma2_(x2, wC.x, acc[20]); acc[21] = fma2_(x2, wC.y, acc[21]);
                acc[22] = fma2_(x2, wD.x, acc[22]); acc[23] = fma2_(x2, wD.y, acc[23]);
                acc[28] = fma2_(x3, wC.x, acc[28]); acc[29] = fma2_(x3, wC.y, acc[29]);
                acc[30] = fma2_(x3, wD.x, acc[30]); acc[31] = fma2_(x3, wD.y, acc[31]);
            }
            __syncwarp();
#pragma unroll
            for (int j = 0; j < 4; j++) {
                float* row = xg + (4 * q + j) * RPITCH;
#pragma unroll
                for (int u2 = 0; u2 < 8; u2++) {
                    float a0, a1;
                    upk2(acc[j * 8 + u2], a0, a1);
                    int oc = chb + 2 * u2;
                    float v0 = __fadd_rn(__fmul_rn(a0, sc1[oc]),     bi1[oc]);
                    float v1 = __fadd_rn(__fmul_rn(a1, sc1[oc + 1]), bi1[oc + 1]);
                    row[oc]     = fmaxf(v0, 0.0f);
                    row[oc + 1] = fmaxf(v1, 0.0f);
                }
            }
            __syncwarp();
        }

        // ---- layer 2: 64 -> 128 in 2 rounds; reduce-scatter maxpool ----
        const size_t outbase = (size_t)b * 128 * NPOINT + sidx;
#pragma unroll 1
        for (int r = 0; r < 2; r++) {
            const int p = s + 4 * r;              // slice 0..7
            const float* wb = w2v + p * W2SL;
#pragma unroll
            for (int i = 0; i < 32; i++) acc[i] = 0ull;
#pragma unroll 1
            for (int c = 0; c < 64; c++) {
                const ulonglong2* wr = (const ulonglong2*)(wb + c * 16);
                ulonglong2 wA = wr[0], wB = wr[1];
                unsigned long long x0 = pk2(xg[(4 * q + 0) * RPITCH + c], xg[(4 * q + 0) * RPITCH + c]);
                unsigned long long x1 = pk2(xg[(4 * q + 1) * RPITCH + c], xg[(4 * q + 1) * RPITCH + c]);
                unsigned long long x2 = pk2(xg[(4 * q + 2) * RPITCH + c], xg[(4 * q + 2) * RPITCH + c]);
                unsigned long long x3 = pk2(xg[(4 * q + 3) * RPITCH + c], xg[(4 * q + 3) * RPITCH + c]);
                acc[0]  = fma2_(x0, wA.x, acc[0]);  acc[1]  = fma2_(x0, wA.y, acc[1]);
                acc[2]  = fma2_(x0, wB.x, acc[2]);  acc[3]  = fma2_(x0, wB.y, acc[3]);
                acc[8]  = fma2_(x1, wA.x, acc[8]);  acc[9]  = fma2_(x1, wA.y, acc[9]);
                acc[10] = fma2_(x1, wB.x, acc[10]); acc[11] = fma2_(x1, wB.y, acc[11]);
                acc[16] = fma2_(x2, wA.x, acc[16]); acc[17] = fma2_(x2, wA.y, acc[17]);
                acc[18] = fma2_(x2, wB.x, acc[18]); acc[19] = fma2_(x2, wB.y, acc[19]);
                acc[24] = fma2_(x3, wA.x, acc[24]); acc[25] = fma2_(x3, wA.y, acc[25]);
                acc[26] = fma2_(x3, wB.x, acc[26]); acc[27] = fma2_(x3, wB.y, acc[27]);
                const ulonglong2* wr2 = (const ulonglong2*)(wb + c * 16 + 8);
                ulonglong2 wC = wr2[0], wD = wr2[1];
                acc[4]  = fma2_(x0, wC.x, acc[4]);  acc[5]  = fma2_(x0, wC.y, acc[5]);
                acc[6]  = fma2_(x0, wD.x, acc[6]);  acc[7]  = fma2_(x0, wD.y, acc[7]);
                acc[12] = fma2_(x1, wC.x, acc[12]); acc[13] = fma2_(x1, wC.y, acc[13]);
                acc[14] = fma2_(x1, wD.x, acc[14]); acc[15] = fma2_(x1, wD.y, acc[15]);
                acc[20] = fma2_(x2, wC.x, acc[20]); acc[21] = fma2_(x2, wC.y, acc[21]);
                acc[22] = fma2_(x2, wD.x, acc[22]); acc[23] = fma2_(x2, wD.y, acc[23]);
                acc[28] = fma2_(x3, wC.x, acc[28]); acc[29] = fma2_(x3, wC.y, acc[29]);
                acc[30] = fma2_(x3, wD.x, acc[30]); acc[31] = fma2_(x3, wD.y, acc[31]);
            }
            float vm[16];
#pragma unroll
            for (int u2 = 0; u2 < 8; u2++) {
                int oc = p * 16 + 2 * u2;
                float scA = sc2[oc], biA = bi2[oc], scB = sc2[oc + 1], biB = bi2[oc + 1];
                float m0 = 0.0f, m1 = 0.0f;   // relu floor
#pragma unroll
                for (int j = 0; j < 4; j++) {
                    float a0, a1;
                    upk2(acc[j * 8 + u2], a0, a1);
                    float v0 = __fadd_rn(__fmul_rn(a0, scA), biA);
                    float v1 = __fadd_rn(__fmul_rn(a1, scB), biB);
                    m0 = fmaxf(m0, fmaxf(v0, 0.0f));
                    m1 = fmaxf(m1, fmaxf(v1, 0.0f));
                }
                vm[2 * u2] = m0; vm[2 * u2 + 1] = m1;
            }
            float B8[8];
#pragma unroll
            for (int i = 0; i < 8; i++) {
                float snd = q2 ? vm[i] : vm[8 + i];
                float got = __shfl_xor_sync(0xffffffffu, snd, 4);
                float kp  = q2 ? vm[8 + i] : vm[i];
                B8[i] = fmaxf(kp, got);
            }
            float C4[4];
#pragma unroll
            for (int i = 0; i < 4; i++) {
                float snd = q1 ? B8[i] : B8[4 + i];
                float got = __shfl_xor_sync(0xffffffffu, snd, 2);
                float kp  = q1 ? B8[4 + i] : B8[i];
                C4[i] = fmaxf(kp, got);
            }
            float D0, D1;
            {
                float snd = q0 ? C4[0] : C4[2];
                float got = __shfl_xor_sync(0xffffffffu, snd, 1);
                float kp  = q0 ? C4[2] : C4[0];
                D0 = fmaxf(kp, got);
                snd = q0 ? C4[1] : C4[3];
                got = __shfl_xor_sync(0xffffffffu, snd, 1);
                kp  = q0 ? C4[3] : C4[1];
                D1 = fmaxf(kp, got);
            }
            const int ch = p * 16 + 2 * q;
            outfeat[outbase + (size_t)ch * NPOINT]       = D0;
            outfeat[outbase + (size_t)(ch + 1) * NPOINT] = D1;
        }

        u = nxt;
    }
}

// ==================================================================
// launch
// ==================================================================
extern "C" void kernel_launch(void* const* d_in, const int* in_sizes, int n_in,
                              void* d_out, int out_size)
{
    (void)in_sizes; (void)n_in; (void)out_size;
    const float* xyz  = (const float*)d_in[0];
    const float* feat = (const float*)d_in[1];
    const float* w0 = (const float*)d_in[2];
    const float* s0 = (const float*)d_in[3];
    const float* b0 = (const float*)d_in[4];
    const float* w1 = (const float*)d_in[5];
    const float* s1 = (const float*)d_in[6];
    const float* b1 = (const float*)d_in[7];
    const float* w2 = (const float*)d_in[8];
    const float* s2 = (const float*)d_in[9];
    const float* b2 = (const float*)d_in[10];

    float* out     = (float*)d_out;
    float* newxyz  = out;                            // (B, NPOINT, 3)
    float* outfeat = out + (size_t)BB * NPOINT * 3;  // (B, 128, NPOINT)

    const int FUSED_SMEM = (4 * W0SL + 4 * W1SL + 8 * W2SL + 512 +
                            16 * 32 * RPITCH) * 4;   // ~205,824 B
    cudaFuncSetAttribute(fused_kernel, cudaFuncAttributeMaxDynamicSharedMemorySize,
                         FUSED_SMEM);

    resetk<<<1, 32>>>();
    fused_kernel<<<BB + MLP_BLOCKS, 512, FUSED_SMEM>>>(
        xyz, feat, w0, s0, b0, w1, s1, b1, w2, s2, b2, newxyz, outfeat);
}